// round 7
// baseline (speedup 1.0000x reference)
#include <cuda_runtime.h>
#include <math.h>
#include <stdint.h>

#define HW 16384          // 64*256 pixels per (batch, channel) plane

// ---------------- scratch (static device globals; no allocation allowed) ----
__device__ float g_Qb[4*128*HW];
__device__ float g_Kb[4*128*HW];
__device__ float g_Vb[4*128*HW];
__device__ float g_Ob[4*128*HW];
__device__ float g_Y [4*256*HW];
__device__ float g_F [(size_t)4*768*HW];
__device__ float g_WA [384*128], g_SgA[384], g_CA[384];
__device__ float g_WIN[256*128], g_SgI[256], g_CI[256];

// ---------------- small helpers --------------------------------------------
__device__ __forceinline__ uint32_t smem_u32(const void* p) {
    return (uint32_t)__cvta_generic_to_shared(p);
}
__device__ __forceinline__ void cp16(uint32_t dst, const void* src) {
    asm volatile("cp.async.cg.shared.global [%0], [%1], 16;\n" :: "r"(dst), "l"(src));
}
__device__ __forceinline__ void cp_commit() { asm volatile("cp.async.commit_group;\n"); }
__device__ __forceinline__ void cp_wait1()  { asm volatile("cp.async.wait_group 1;\n"); }

__device__ __forceinline__ void mma_tf32(float* c, const uint32_t* a, const uint32_t* b) {
    asm volatile("mma.sync.aligned.m16n8k8.row.col.f32.tf32.tf32.f32 "
        "{%0,%1,%2,%3}, {%4,%5,%6,%7}, {%8,%9}, {%0,%1,%2,%3};"
        : "+f"(c[0]), "+f"(c[1]), "+f"(c[2]), "+f"(c[3])
        : "r"(a[0]), "r"(a[1]), "r"(a[2]), "r"(a[3]), "r"(b[0]), "r"(b[1]));
}
__device__ __forceinline__ void ldsm4(uint32_t* r, uint32_t addr) {
    asm volatile("ldmatrix.sync.aligned.m8n8.x4.shared.b16 {%0,%1,%2,%3}, [%4];"
        : "=r"(r[0]), "=r"(r[1]), "=r"(r[2]), "=r"(r[3]) : "r"(addr));
}
__device__ __forceinline__ float fexp2(float x) {
    float r; asm("ex2.approx.ftz.f32 %0, %1;" : "=f"(r) : "f"(x)); return r;
}

// ---------------- fold LN gamma/beta into GEMM weights ---------------------
__global__ void prep_kernel(const float* __restrict__ wq,  const float* __restrict__ bq,
                            const float* __restrict__ wkv, const float* __restrict__ bkv,
                            const float* __restrict__ an_g, const float* __restrict__ an_b,
                            const float* __restrict__ anc_g, const float* __restrict__ anc_b,
                            const float* __restrict__ w_in, const float* __restrict__ b_in,
                            const float* __restrict__ fn_g, const float* __restrict__ fn_b) {
    int r = blockIdx.x, t = threadIdx.x;   // 640 blocks x 128 threads
    __shared__ float red[2][4];
    float wl, gg, bb, extra;
    float *Wdst, *Sgd, *Cd;
    if (r < 128)      { wl = wq [r*128 + t];        gg = an_g[t];  bb = an_b[t];  extra = bq [r];
                        Wdst = g_WA  + r*128;        Sgd = g_SgA + r;  Cd = g_CA + r; }
    else if (r < 384) { int rr = r - 128;
                        wl = wkv[rr*128 + t];       gg = anc_g[t]; bb = anc_b[t]; extra = bkv[rr];
                        Wdst = g_WA  + r*128;        Sgd = g_SgA + r;  Cd = g_CA + r; }
    else              { int rr = r - 384;
                        wl = w_in[rr*128 + t];      gg = fn_g[t];  bb = fn_b[t];  extra = b_in[rr];
                        Wdst = g_WIN + rr*128;       Sgd = g_SgI + rr; Cd = g_CI + rr; }
    float wg = wl * gg;
    Wdst[t] = wg;
    float s1 = wg, s2 = wl * bb;
    #pragma unroll
    for (int off = 16; off; off >>= 1) {
        s1 += __shfl_down_sync(0xffffffffu, s1, off);
        s2 += __shfl_down_sync(0xffffffffu, s2, off);
    }
    if ((t & 31) == 0) { red[0][t >> 5] = s1; red[1][t >> 5] = s2; }
    __syncthreads();
    if (t == 0) {
        float a = red[0][0] + red[0][1] + red[0][2] + red[0][3];
        float b = red[1][0] + red[1][1] + red[1][2] + red[1][3];
        *Sgd = a; *Cd = b + extra;
    }
}

// ---------------- tf32 tensor-core GEMM, 32x32 warp tiles, high occupancy ---
// 256 threads = 8 warps of 32x32; shapes: S1 BM=128/BN=64 (4x2), S2 BM=256/BN=32 (8x1)
template<int K, int MODE, int BM, int BN>
__global__ void __launch_bounds__(256, (BM == 128) ? 3 : 2)
gemm_tc(const float* __restrict__ A, const float* __restrict__ B,
        float* __restrict__ O0, float* __restrict__ O1, float* __restrict__ O2,
        const float* __restrict__ Sg, const float* __restrict__ Cst,
        const float* __restrict__ X1, const float* __restrict__ X2,
        const float* __restrict__ bias, float eps) {
    constexpr int BK = 16, ST = 3;
    constexpr int KT = K / BK;
    constexpr int ASP = 20;
    constexpr int BSP = BN + 8;
    constexpr int ASZ = BM * ASP;
    constexpr int BSZ = BK * BSP;
    constexpr int NA = BM / 64;              // A float4 loads per thread (BM*4/256)
    constexpr int BF4 = 16 * (BN / 4);       // B float4s per stage (256 or 128)
    constexpr int WNC = BN / 32;             // warps along N
    constexpr bool STATS = (MODE == 0 || MODE == 2);
    constexpr int SH = STATS ? (256 / BN) : 1;
    constexpr int RT = STATS ? (16 / SH) : 1;
    extern __shared__ float smf[];
    float* As = smf;
    float* Bs = smf + ST * ASZ;
    __shared__ float sst[STATS ? 2 : 1][SH][STATS ? BN : 1];

    int tid = threadIdx.x, lane = tid & 31, wid = tid >> 5;
    int wm = wid / WNC, wn = wid % WNC;
    int n0 = blockIdx.x * BN, m0 = blockIdx.y * BM, u = blockIdx.z;
    const float* Ap = A + (size_t)m0 * K;
    const float* Bp;
    if (MODE == 0) Bp = (u < 2 ? X1 : X2) + (size_t)(u & 1) * 128 * HW + n0;
    else           Bp = B + (size_t)u * K * HW + n0;

    float acc[2][4][4];
    #pragma unroll
    for (int i = 0; i < 2; i++)
        #pragma unroll
        for (int j = 0; j < 4; j++)
            #pragma unroll
            for (int e = 0; e < 4; e++) acc[i][j][e] = 0.f;

    int ar[NA], ac[NA];
    #pragma unroll
    for (int i = 0; i < NA; i++) {
        int idx = tid + i * 256;
        ar[i] = idx >> 2; ac[i] = (idx & 3) << 2;
    }
    int br = tid / (BN / 4), bc = (tid % (BN / 4)) << 2;
    bool bact = (BF4 >= 256) || (tid < BF4);

    int sc = tid % (STATS ? BN : 1), sg = tid / (STATS ? BN : 256);
    float s_sum = 0.f, s_sq = 0.f;
    int lm = lane >> 3;
    int loff = (((lane & 7) + (lm & 1) * 8)) * ASP + (lm >> 1) * 4;
    uint32_t as_base = smem_u32(As);

    #define PREFETCH(sidx, k0)                                                     \
        {   _Pragma("unroll")                                                      \
            for (int i = 0; i < NA; i++)                                           \
                cp16(smem_u32(&As[(sidx) * ASZ + ar[i] * ASP + ac[i]]),            \
                     Ap + (size_t)ar[i] * K + (k0) + ac[i]);                       \
            if (bact)                                                              \
                cp16(smem_u32(&Bs[(sidx) * BSZ + br * BSP + bc]),                  \
                     Bp + (size_t)((k0) + br) * HW + bc);                          \
        }

    PREFETCH(0, 0); cp_commit();
    if (KT > 1) PREFETCH(1, BK);
    cp_commit();

    for (int kt = 0; kt < KT; kt++) {
        cp_wait1();
        __syncthreads();
        int st = kt % ST;
        const float* bs = Bs + st * BSZ;
        if (STATS) {
            #pragma unroll
            for (int rr = 0; rr < RT; rr++) {
                float v = bs[(sg * RT + rr) * BSP + sc];
                s_sum += v; s_sq += v * v;
            }
        }
        uint32_t abase = as_base + (uint32_t)(st * ASZ + wm * 32 * ASP + loff) * 4;
        #pragma unroll
        for (int s8 = 0; s8 < 2; s8++) {
            uint32_t a[2][4], b[4][2];
            #pragma unroll
            for (int mt = 0; mt < 2; mt++)
                ldsm4(a[mt], abase + (uint32_t)(mt * 16 * ASP + s8 * 8) * 4);
            #pragma unroll
            for (int nt = 0; nt < 4; nt++) {
                const float* bp = bs + (s8 * 8 + (lane & 3)) * BSP
                                     + wn * 32 + nt * 8 + (lane >> 2);
                b[nt][0] = __float_as_uint(bp[0]);
                b[nt][1] = __float_as_uint(bp[4 * BSP]);
            }
            #pragma unroll
            for (int mt = 0; mt < 2; mt++)
                #pragma unroll
                for (int nt = 0; nt < 4; nt++)
                    mma_tf32(acc[mt][nt], a[mt], b[nt]);
        }
        if (kt + 2 < KT) PREFETCH((kt + 2) % ST, (kt + 2) * BK);
        cp_commit();
    }
    #undef PREFETCH

    // ---- finalize per-pixel LN stats (MODE 0/2) ----
    if (STATS) {
        sst[0][sg][sc] = s_sum;
        sst[1][sg][sc] = s_sq;
        __syncthreads();
        if (tid < BN) {
            float S = 0.f, SS = 0.f;
            #pragma unroll
            for (int g = 0; g < SH; g++) { S += sst[0][g][tid]; SS += sst[1][g][tid]; }
            float m = S * (1.f / 128.f);
            float var = SS * (1.f / 128.f) - m * m;
            sst[0][0][tid] = m;
            sst[1][0][tid] = rsqrtf(var + eps);
        }
        __syncthreads();
    }

    // ---- epilogue ----
    #pragma unroll
    for (int mt = 0; mt < 2; mt++) {
        #pragma unroll
        for (int half = 0; half < 2; half++) {
            int row = m0 + wm * 32 + mt * 16 + (lane >> 2) + half * 8;
            float sgr = 0.f, cstr = 0.f, br2 = 0.f;
            if (MODE == 0 || MODE == 2) { sgr = Sg[row]; cstr = Cst[row]; }
            else br2 = bias[row];
            #pragma unroll
            for (int nt = 0; nt < 4; nt++) {
                #pragma unroll
                for (int e = 0; e < 2; e++) {
                    int pl = wn * 32 + nt * 8 + (lane & 3) * 2 + e;
                    int p = n0 + pl;
                    float v = acc[mt][nt][half * 2 + e];
                    if (MODE == 0) {
                        float mv = sst[0][0][pl], rv = sst[1][0][pl];
                        v = rv * v + (cstr - mv * rv * sgr);
                        if (row < 128)       O0[((size_t)u * 128 + row) * HW + p] = v;
                        else if (row < 256)  O1[((size_t)(u ^ 2) * 128 + (row - 128)) * HW + p] = v;
                        else                 O2[((size_t)(u ^ 2) * 128 + (row - 256)) * HW + p] = v;
                    } else if (MODE == 1) {
                        float res = ((u < 2 ? X1 : X2))[((size_t)(u & 1) * 128 + row) * HW + p];
                        size_t idx = ((size_t)u * 128 + row) * HW + p;
                        O0[idx] = v + br2 + res;
                    } else if (MODE == 2) {
                        float mv = sst[0][0][pl], rv = sst[1][0][pl];
                        v = rv * v + (cstr - mv * rv * sgr);
                        v = v / (1.f + __expf(-v));
                        O0[((size_t)u * 256 + row) * HW + p] = v;
                    } else if (MODE == 3) {
                        v += br2;
                        v = v / (1.f + __expf(-v));
                        size_t idx = ((size_t)u * 256 + row) * HW + p;
                        O0[idx] = O0[idx] + v;
                    } else {
                        v += br2;
                        size_t idx = ((size_t)u * 128 + row) * HW + p;
                        O0[idx] += v;
                    }
                }
            }
        }
    }
}

// ---------------- attention via tf32 MMA (no-max softmax: scores tiny) ------
#define KS_P 36
#define VS_P 40
#define PS_P 68
#define SM_KS 0
#define SM_VS (256*KS_P)
#define SM_PS (SM_VS + 256*VS_P)
#define SM_V2 (SM_PS + 8*32*PS_P)
#define SM_VSUM (SM_V2 + 256)
#define ATTN_SMEM ((SM_VSUM + 32) * 4)

__global__ void __launch_bounds__(256)
attn_mma(const float* __restrict__ Q, const float* __restrict__ K,
         const float* __restrict__ V, float* __restrict__ O) {
    int blk = blockIdx.x;                  // b*256 + n*64 + h
    int h = blk & 63, n = (blk >> 6) & 3, b = blk >> 8;
    size_t base = ((size_t)(b * 128 + n * 32) * 64 + h) * 256;
    extern __shared__ float sm[];
    float* Ks = sm + SM_KS;
    float* Vs = sm + SM_VS;
    float* V2 = sm + SM_V2;
    float* Vsum = sm + SM_VSUM;
    int tid = threadIdx.x, lane = tid & 31, w = tid >> 5;
    float* Pw = sm + SM_PS + w * 32 * PS_P;

    #pragma unroll 4
    for (int dd = 0; dd < 32; dd++) {
        Ks[tid * KS_P + dd] = K[base + dd * HW + tid];
        Vs[tid * VS_P + dd] = V[base + dd * HW + tid];
    }
    __syncthreads();
    {
        float s = 0.f;
        #pragma unroll 8
        for (int jj = 0; jj < 32; jj++) s += Vs[(w * 32 + jj) * VS_P + lane];
        V2[w * 32 + lane] = s;
    }

    const float qs = 0.17677669529663687f * 1.4426950408889634f;
    int i0 = w * 32;
    uint32_t qa[2][4][4];
    #pragma unroll
    for (int mt = 0; mt < 2; mt++)
        #pragma unroll
        for (int kc = 0; kc < 4; kc++) {
            int r0 = i0 + mt * 16 + (lane >> 2);
            int c0 = kc * 8 + (lane & 3);
            qa[mt][kc][0] = __float_as_uint(Q[base + (size_t)c0 * HW + r0] * qs);
            qa[mt][kc][1] = __float_as_uint(Q[base + (size_t)c0 * HW + r0 + 8] * qs);
            qa[mt][kc][2] = __float_as_uint(Q[base + (size_t)(c0 + 4) * HW + r0] * qs);
            qa[mt][kc][3] = __float_as_uint(Q[base + (size_t)(c0 + 4) * HW + r0 + 8] * qs);
        }

    float l_run[2][2] = {{0.f, 0.f}, {0.f, 0.f}};
    float o[2][4][4];
    #pragma unroll
    for (int mt = 0; mt < 2; mt++)
        #pragma unroll
        for (int dt = 0; dt < 4; dt++)
            #pragma unroll
            for (int e = 0; e < 4; e++) o[mt][dt][e] = 0.f;

    for (int jb = 0; jb < 4; jb++) {
        int j0 = jb * 64;
        float s[2][8][4];
        #pragma unroll
        for (int mt = 0; mt < 2; mt++)
            #pragma unroll
            for (int nt = 0; nt < 8; nt++)
                #pragma unroll
                for (int e = 0; e < 4; e++) s[mt][nt][e] = 0.f;
        #pragma unroll
        for (int kc = 0; kc < 4; kc++) {
            uint32_t bf[8][2];
            #pragma unroll
            for (int nt = 0; nt < 8; nt++) {
                int jr = j0 + nt * 8 + (lane >> 2);
                int dc = kc * 8 + (lane & 3);
                bf[nt][0] = __float_as_uint(Ks[jr * KS_P + dc]);
                bf[nt][1] = __float_as_uint(Ks[jr * KS_P + dc + 4]);
            }
            #pragma unroll
            for (int mt = 0; mt < 2; mt++)
                #pragma unroll
                for (int nt = 0; nt < 8; nt++)
                    mma_tf32(s[mt][nt], qa[mt][kc], bf[nt]);
        }
        #pragma unroll
        for (int mt = 0; mt < 2; mt++) {
            #pragma unroll
            for (int hf = 0; hf < 2; hf++) {
                int row = mt * 16 + (lane >> 2) + hf * 8;
                float rs = 0.f;
                #pragma unroll
                for (int nt = 0; nt < 8; nt++) {
                    float p0 = fexp2(s[mt][nt][2 * hf]);
                    float p1 = fexp2(s[mt][nt][2 * hf + 1]);
                    rs += p0 + p1;
                    Pw[row * PS_P + nt * 8 + (lane & 3) * 2]     = p0;
                    Pw[row * PS_P + nt * 8 + (lane & 3) * 2 + 1] = p1;
                }
                rs += __shfl_xor_sync(0xffffffffu, rs, 1);
                rs += __shfl_xor_sync(0xffffffffu, rs, 2);
                l_run[mt][hf] += rs;
            }
        }
        __syncwarp();
        #pragma unroll
        for (int jc = 0; jc < 8; jc++) {
            uint32_t pa[2][4];
            #pragma unroll
            for (int mt = 0; mt < 2; mt++) {
                int r = mt * 16 + (lane >> 2);
                int c = jc * 8 + (lane & 3);
                pa[mt][0] = __float_as_uint(Pw[r * PS_P + c]);
                pa[mt][1] = __float_as_uint(Pw[(r + 8) * PS_P + c]);
                pa[mt][2] = __float_as_uint(Pw[r * PS_P + c + 4]);
                pa[mt][3] = __float_as_uint(Pw[(r + 8) * PS_P + c + 4]);
            }
            uint32_t vb[4][2];
            #pragma unroll
            for (int dt = 0; dt < 4; dt++) {
                int jr = j0 + jc * 8 + (lane & 3);
                int dc = dt * 8 + (lane >> 2);
                vb[dt][0] = __float_as_uint(Vs[jr * VS_P + dc]);
                vb[dt][1] = __float_as_uint(Vs[(jr + 4) * VS_P + dc]);
            }
            #pragma unroll
            for (int mt = 0; mt < 2; mt++)
                #pragma unroll
                for (int dt = 0; dt < 4; dt++)
                    mma_tf32(o[mt][dt], pa[mt], vb[dt]);
        }
        __syncwarp();
    }

    #pragma unroll
    for (int mt = 0; mt < 2; mt++)
        #pragma unroll
        for (int hf = 0; hf < 2; hf++) {
            float inv = 1.f / l_run[mt][hf];
            int row = mt * 16 + (lane >> 2) + hf * 8;
            #pragma unroll
            for (int dt = 0; dt < 4; dt++) {
                Pw[row * 36 + dt * 8 + (lane & 3) * 2]     = o[mt][dt][2 * hf] * inv;
                Pw[row * 36 + dt * 8 + (lane & 3) * 2 + 1] = o[mt][dt][2 * hf + 1] * inv;
            }
        }
    __syncthreads();
    if (tid < 32) {
        float s = 0.f;
        #pragma unroll
        for (int ww = 0; ww < 8; ww++) s += V2[ww * 32 + tid];
        Vsum[tid] = s;
    }
    __syncthreads();
    const float eps = 1e-6f;
    const float norm = 1.f / (1.f + 256.f * eps);
    #pragma unroll 4
    for (int d = 0; d < 32; d++) {
        float val = (Pw[lane * 36 + d] + eps * Vsum[d]) * norm;
        O[base + (size_t)d * HW + i0 + lane] = val;
    }
}

// ---------------- depthwise 3x3 / 5x5 / 7x7 (SAME, zero pad), 8x64 tiles ----
__global__ void dw_kernel(const float* __restrict__ Y,
                          const float* __restrict__ w3, const float* __restrict__ b3,
                          const float* __restrict__ w5, const float* __restrict__ b5,
                          const float* __restrict__ w7, const float* __restrict__ b7,
                          float* __restrict__ F) {
    __shared__ float S[14][70];
    __shared__ float wgt[84];
    int z = blockIdx.z; int ch = z & 255; int u = z >> 8;
    int w0 = blockIdx.x * 64, h0 = blockIdx.y * 8;
    int tid = threadIdx.x;
    if (tid < 9)       wgt[tid] = w3[ch * 9 + tid];
    else if (tid < 34) wgt[tid] = w5[ch * 25 + tid - 9];
    else if (tid < 83) wgt[tid] = w7[ch * 49 + tid - 34];
    const float* Yp = Y + ((size_t)u * 256 + ch) * HW;
    for (int i = tid; i < 980; i += 256) {
        int r = i / 70, c = i % 70;
        int gh = h0 - 3 + r, gw = w0 - 3 + c;
        float v = 0.f;
        if ((unsigned)gh < 64u && (unsigned)gw < 256u) v = Yp[gh * 256 + gw];
        S[r][c] = v;
    }
    __syncthreads();
    int tx = tid & 63, ty = tid >> 6;
    float bb3 = b3[ch], bb5 = b5[ch], bb7 = b7[ch];
    #pragma unroll
    for (int rr = 0; rr < 2; rr++) {
        int rc = ty + rr * 4 + 3, cc = tx + 3;
        float f3 = bb3, f5 = bb5, f7 = bb7;
        #pragma unroll
        for (int dy = -3; dy <= 3; dy++)
            #pragma unroll
            for (int dx = -3; dx <= 3; dx++) {
                float v = S[rc + dy][cc + dx];
                f7 += v * wgt[34 + (dy + 3) * 7 + (dx + 3)];
                if (dy >= -2 && dy <= 2 && dx >= -2 && dx <= 2)
                    f5 += v * wgt[9 + (dy + 2) * 5 + (dx + 2)];
                if (dy >= -1 && dy <= 1 && dx >= -1 && dx <= 1)
                    f3 += v * wgt[(dy + 1) * 3 + (dx + 1)];
            }
        size_t pix = (size_t)(h0 + ty + rr * 4) * 256 + (w0 + tx);
        size_t ob = (size_t)u * 768 * HW + pix;
        F[ob + (size_t) ch        * HW] = f3;
        F[ob + (size_t)(256 + ch) * HW] = f5;
        F[ob + (size_t)(512 + ch) * HW] = f7;
    }
}

// ---------------- host launcher --------------------------------------------
extern "C" void kernel_launch(void* const* d_in, const int* in_sizes, int n_in,
                              void* d_out, int out_size) {
    const float* feats1 = (const float*)d_in[0];
    const float* feats2 = (const float*)d_in[1];
    const float* an_g  = (const float*)d_in[2];
    const float* an_b  = (const float*)d_in[3];
    const float* anc_g = (const float*)d_in[4];
    const float* anc_b = (const float*)d_in[5];
    const float* wq    = (const float*)d_in[6];
    const float* bq    = (const float*)d_in[7];
    const float* wkv   = (const float*)d_in[8];
    const float* bkv   = (const float*)d_in[9];
    const float* wo    = (const float*)d_in[10];
    const float* bo    = (const float*)d_in[11];
    const float* fn_g  = (const float*)d_in[12];
    const float* fn_b  = (const float*)d_in[13];
    const float* w_in  = (const float*)d_in[14];
    const float* b_in  = (const float*)d_in[15];
    const float* w_dw3 = (const float*)d_in[16];
    const float* b_dw3 = (const float*)d_in[17];
    const float* w_dw5 = (const float*)d_in[18];
    const float* b_dw5 = (const float*)d_in[19];
    const float* w_dw7 = (const float*)d_in[20];
    const float* b_dw7 = (const float*)d_in[21];
    const float* w_pw  = (const float*)d_in[22];
    const float* b_pw  = (const float*)d_in[23];
    const float* w_out = (const float*)d_in[24];
    const float* b_out = (const float*)d_in[25];
    float* dout = (float*)d_out;

    float *Q, *K, *V, *O, *Y, *F, *WA, *SgA, *CA, *WIN, *SgI, *CI;
    cudaGetSymbolAddress((void**)&Q,  g_Qb);
    cudaGetSymbolAddress((void**)&K,  g_Kb);
    cudaGetSymbolAddress((void**)&V,  g_Vb);
    cudaGetSymbolAddress((void**)&O,  g_Ob);
    cudaGetSymbolAddress((void**)&Y,  g_Y);
    cudaGetSymbolAddress((void**)&F,  g_F);
    cudaGetSymbolAddress((void**)&WA, g_WA);
    cudaGetSymbolAddress((void**)&SgA, g_SgA);
    cudaGetSymbolAddress((void**)&CA, g_CA);
    cudaGetSymbolAddress((void**)&WIN, g_WIN);
    cudaGetSymbolAddress((void**)&SgI, g_SgI);
    cudaGetSymbolAddress((void**)&CI, g_CI);

    const int smS1 = 3 * (128 * 20 + 16 * 72) * 4;   // 44544 B (BM=128/BN=64)
    const int smS2 = 3 * (256 * 20 + 16 * 40) * 4;   // 69120 B (BM=256/BN=32)
    cudaFuncSetAttribute((const void*)gemm_tc<128, 0, 128, 64>, cudaFuncAttributeMaxDynamicSharedMemorySize, smS1);
    cudaFuncSetAttribute((const void*)gemm_tc<128, 1, 128, 64>, cudaFuncAttributeMaxDynamicSharedMemorySize, smS1);
    cudaFuncSetAttribute((const void*)gemm_tc<128, 2, 256, 32>, cudaFuncAttributeMaxDynamicSharedMemorySize, smS2);
    cudaFuncSetAttribute((const void*)gemm_tc<768, 3, 256, 32>, cudaFuncAttributeMaxDynamicSharedMemorySize, smS2);
    cudaFuncSetAttribute((const void*)gemm_tc<256, 4, 128, 64>, cudaFuncAttributeMaxDynamicSharedMemorySize, smS1);
    cudaFuncSetAttribute((const void*)attn_mma, cudaFuncAttributeMaxDynamicSharedMemorySize, ATTN_SMEM);

    // 1. weight prep
    prep_kernel<<<640, 128>>>(wq, bq, wkv, bkv, an_g, an_b, anc_g, anc_b,
                              w_in, b_in, fn_g, fn_b);
    // 2. fused LN(in-kernel stats) + q/kv projection (B read from feats)
    gemm_tc<128, 0, 128, 64><<<dim3(256, 3, 4), 256, smS1>>>(WA, nullptr, Q, K, V, SgA, CA,
                                                             feats1, feats2, nullptr, 1e-6f);
    // 3. attention (tf32 MMA flash, no-max softmax)
    attn_mma<<<1024, 256, ATTN_SMEM>>>(Q, K, V, O);
    // 4. output projection + residual(feats) -> d_out
    gemm_tc<128, 1, 128, 64><<<dim3(256, 1, 4), 256, smS1>>>(wo, O, dout, nullptr, nullptr,
                                                             nullptr, nullptr,
                                                             feats1, feats2, bo, 0.f);
    // 5. fused LN(in-kernel stats) + w_in + SiLU -> Y
    gemm_tc<128, 2, 256, 32><<<dim3(512, 1, 4), 256, smS2>>>(WIN, dout, Y, nullptr, nullptr,
                                                             SgI, CI, nullptr, nullptr, nullptr, 1e-5f);
    // 6. depthwise 3/5/7 -> F (768 channels)
    dw_kernel<<<dim3(4, 8, 1024), 256>>>(Y, w_dw3, b_dw3, w_dw5, b_dw5, w_dw7, b_dw7, F);
    // 7. pointwise GEMM (K=768) + SiLU + residual into Y
    gemm_tc<768, 3, 256, 32><<<dim3(512, 1, 4), 256, smS2>>>(w_pw, F, Y, nullptr, nullptr,
                                                             nullptr, nullptr, nullptr, nullptr, b_pw, 0.f);
    // 8. w_out GEMM (K=256), accumulate into d_out
    gemm_tc<256, 4, 128, 64><<<dim3(256, 1, 4), 256, smS1>>>(w_out, Y, dout, nullptr, nullptr,
                                                             nullptr, nullptr, nullptr, nullptr, b_out, 0.f);
}

// round 8
// speedup vs baseline: 1.1651x; 1.1651x over previous
#include <cuda_runtime.h>
#include <math.h>
#include <stdint.h>

#define HW 16384          // 64*256 pixels per (batch, channel) plane

// ---------------- scratch (static device globals; no allocation allowed) ----
__device__ float g_Qb[4*128*HW];
__device__ float g_Kb[4*128*HW];
__device__ float g_Vb[4*128*HW];
__device__ float g_Ob[4*128*HW];
__device__ float g_Y [4*256*HW];
__device__ float g_F [(size_t)4*768*HW];
__device__ float g_WA [384*128], g_SgA[384], g_CA[384];
__device__ float g_WIN[256*128], g_SgI[256], g_CI[256];

// ---------------- small helpers --------------------------------------------
__device__ __forceinline__ uint32_t smem_u32(const void* p) {
    return (uint32_t)__cvta_generic_to_shared(p);
}
__device__ __forceinline__ void cp16(uint32_t dst, const void* src) {
    asm volatile("cp.async.cg.shared.global [%0], [%1], 16;\n" :: "r"(dst), "l"(src));
}
__device__ __forceinline__ void cp_commit() { asm volatile("cp.async.commit_group;\n"); }
__device__ __forceinline__ void cp_wait1()  { asm volatile("cp.async.wait_group 1;\n"); }

__device__ __forceinline__ void mma_tf32(float* c, const uint32_t* a, const uint32_t* b) {
    asm volatile("mma.sync.aligned.m16n8k8.row.col.f32.tf32.tf32.f32 "
        "{%0,%1,%2,%3}, {%4,%5,%6,%7}, {%8,%9}, {%0,%1,%2,%3};"
        : "+f"(c[0]), "+f"(c[1]), "+f"(c[2]), "+f"(c[3])
        : "r"(a[0]), "r"(a[1]), "r"(a[2]), "r"(a[3]), "r"(b[0]), "r"(b[1]));
}
__device__ __forceinline__ void ldsm4(uint32_t* r, uint32_t addr) {
    asm volatile("ldmatrix.sync.aligned.m8n8.x4.shared.b16 {%0,%1,%2,%3}, [%4];"
        : "=r"(r[0]), "=r"(r[1]), "=r"(r[2]), "=r"(r[3]) : "r"(addr));
}
__device__ __forceinline__ float fexp2(float x) {
    float r; asm("ex2.approx.ftz.f32 %0, %1;" : "=f"(r) : "f"(x)); return r;
}

// ---------------- fold LN gamma/beta into GEMM weights ---------------------
__global__ void prep_kernel(const float* __restrict__ wq,  const float* __restrict__ bq,
                            const float* __restrict__ wkv, const float* __restrict__ bkv,
                            const float* __restrict__ an_g, const float* __restrict__ an_b,
                            const float* __restrict__ anc_g, const float* __restrict__ anc_b,
                            const float* __restrict__ w_in, const float* __restrict__ b_in,
                            const float* __restrict__ fn_g, const float* __restrict__ fn_b) {
    int r = blockIdx.x, t = threadIdx.x;   // 640 blocks x 128 threads
    __shared__ float red[2][4];
    float wl, gg, bb, extra;
    float *Wdst, *Sgd, *Cd;
    if (r < 128)      { wl = wq [r*128 + t];        gg = an_g[t];  bb = an_b[t];  extra = bq [r];
                        Wdst = g_WA  + r*128;        Sgd = g_SgA + r;  Cd = g_CA + r; }
    else if (r < 384) { int rr = r - 128;
                        wl = wkv[rr*128 + t];       gg = anc_g[t]; bb = anc_b[t]; extra = bkv[rr];
                        Wdst = g_WA  + r*128;        Sgd = g_SgA + r;  Cd = g_CA + r; }
    else              { int rr = r - 384;
                        wl = w_in[rr*128 + t];      gg = fn_g[t];  bb = fn_b[t];  extra = b_in[rr];
                        Wdst = g_WIN + rr*128;       Sgd = g_SgI + rr; Cd = g_CI + rr; }
    float wg = wl * gg;
    Wdst[t] = wg;
    float s1 = wg, s2 = wl * bb;
    #pragma unroll
    for (int off = 16; off; off >>= 1) {
        s1 += __shfl_down_sync(0xffffffffu, s1, off);
        s2 += __shfl_down_sync(0xffffffffu, s2, off);
    }
    if ((t & 31) == 0) { red[0][t >> 5] = s1; red[1][t >> 5] = s2; }
    __syncthreads();
    if (t == 0) {
        float a = red[0][0] + red[0][1] + red[0][2] + red[0][3];
        float b = red[1][0] + red[1][1] + red[1][2] + red[1][3];
        *Sgd = a; *Cd = b + extra;
    }
}

// ---------------- tf32 tensor-core GEMM (round-5 proven config) -------------
// 256 threads, 64x32 warp tiles; S1 BM=128/BN=128 (2x4 warps), S2 BM=256/BN=64 (4x2)
template<int K, int MODE, int BM, int BN>
__global__ void __launch_bounds__(256)
gemm_tc(const float* __restrict__ A, const float* __restrict__ B,
        float* __restrict__ O0, float* __restrict__ O1, float* __restrict__ O2,
        const float* __restrict__ Sg, const float* __restrict__ Cst,
        const float* __restrict__ X1, const float* __restrict__ X2,
        const float* __restrict__ bias, float eps) {
    constexpr int BK = 16, ST = 3;
    constexpr int KT = K / BK;
    constexpr int ASP = 20;
    constexpr int BSP = BN + 8;
    constexpr int ASZ = BM * ASP;
    constexpr int BSZ = BK * BSP;
    constexpr int NA = BM / 64;
    constexpr int NB = BN / 64;
    constexpr int WN = (BM == 128) ? 4 : 2;
    constexpr bool STATS = (MODE == 0 || MODE == 2);
    constexpr int SH = (BN == 64) ? 4 : 2;
    constexpr int RT = 16 / SH;
    extern __shared__ float smf[];
    float* As = smf;
    float* Bs = smf + ST * ASZ;
    __shared__ float sst[STATS ? 2 : 1][STATS ? SH : 1][STATS ? BN : 1];

    int tid = threadIdx.x, lane = tid & 31, wid = tid >> 5;
    int wm = wid / WN, wn = wid % WN;
    int n0 = blockIdx.x * BN, m0 = blockIdx.y * BM, u = blockIdx.z;
    const float* Ap = A + (size_t)m0 * K;
    const float* Bp;
    if (MODE == 0) Bp = (u < 2 ? X1 : X2) + (size_t)(u & 1) * 128 * HW + n0;
    else           Bp = B + (size_t)u * K * HW + n0;

    float acc[4][4][4];
    #pragma unroll
    for (int i = 0; i < 4; i++)
        #pragma unroll
        for (int j = 0; j < 4; j++)
            #pragma unroll
            for (int e = 0; e < 4; e++) acc[i][j][e] = 0.f;

    int ar[NA], ac[NA], br[NB], bc[NB];
    #pragma unroll
    for (int i = 0; i < NA; i++) {
        int idx = tid + i * 256;
        ar[i] = idx >> 2; ac[i] = (idx & 3) << 2;
    }
    #pragma unroll
    for (int i = 0; i < NB; i++) {
        int idx = tid + i * 256;
        br[i] = idx / (BN / 4); bc[i] = (idx % (BN / 4)) << 2;
    }
    int sc = tid % BN, sg = tid / BN;
    float s_sum = 0.f, s_sq = 0.f;
    int lm = lane >> 3;
    int loff = (((lane & 7) + (lm & 1) * 8)) * ASP + (lm >> 1) * 4;
    uint32_t as_base = smem_u32(As);

    #define PREFETCH(sidx, k0)                                                     \
        {   _Pragma("unroll")                                                      \
            for (int i = 0; i < NA; i++)                                           \
                cp16(smem_u32(&As[(sidx) * ASZ + ar[i] * ASP + ac[i]]),            \
                     Ap + (size_t)ar[i] * K + (k0) + ac[i]);                       \
            _Pragma("unroll")                                                      \
            for (int i = 0; i < NB; i++)                                           \
                cp16(smem_u32(&Bs[(sidx) * BSZ + br[i] * BSP + bc[i]]),            \
                     Bp + (size_t)((k0) + br[i]) * HW + bc[i]);                    \
        }

    PREFETCH(0, 0); cp_commit();
    if (KT > 1) PREFETCH(1, BK);
    cp_commit();

    for (int kt = 0; kt < KT; kt++) {
        cp_wait1();
        __syncthreads();
        int st = kt % ST;
        const float* bs = Bs + st * BSZ;
        if (STATS) {
            #pragma unroll
            for (int rr = 0; rr < RT; rr++) {
                float v = bs[(sg * RT + rr) * BSP + sc];
                s_sum += v; s_sq += v * v;
            }
        }
        uint32_t abase = as_base + (uint32_t)(st * ASZ + wm * 64 * ASP + loff) * 4;
        #pragma unroll
        for (int s8 = 0; s8 < 2; s8++) {
            uint32_t a[4][4], b[4][2];
            #pragma unroll
            for (int mt = 0; mt < 4; mt++)
                ldsm4(a[mt], abase + (uint32_t)(mt * 16 * ASP + s8 * 8) * 4);
            #pragma unroll
            for (int nt = 0; nt < 4; nt++) {
                const float* bp = bs + (s8 * 8 + (lane & 3)) * BSP
                                     + wn * 32 + nt * 8 + (lane >> 2);
                b[nt][0] = __float_as_uint(bp[0]);
                b[nt][1] = __float_as_uint(bp[4 * BSP]);
            }
            #pragma unroll
            for (int mt = 0; mt < 4; mt++)
                #pragma unroll
                for (int nt = 0; nt < 4; nt++)
                    mma_tf32(acc[mt][nt], a[mt], b[nt]);
        }
        if (kt + 2 < KT) PREFETCH((kt + 2) % ST, (kt + 2) * BK);
        cp_commit();
    }
    #undef PREFETCH

    if (STATS) {
        sst[0][sg][sc] = s_sum;
        sst[1][sg][sc] = s_sq;
        __syncthreads();
        if (tid < BN) {
            float S = 0.f, SS = 0.f;
            #pragma unroll
            for (int g = 0; g < SH; g++) { S += sst[0][g][tid]; SS += sst[1][g][tid]; }
            float m = S * (1.f / 128.f);
            float var = SS * (1.f / 128.f) - m * m;
            sst[0][0][tid] = m;
            sst[1][0][tid] = rsqrtf(var + eps);
        }
        __syncthreads();
    }

    #pragma unroll
    for (int mt = 0; mt < 4; mt++) {
        #pragma unroll
        for (int half = 0; half < 2; half++) {
            int row = m0 + wm * 64 + mt * 16 + (lane >> 2) + half * 8;
            float sgr = 0.f, cstr = 0.f, br2 = 0.f;
            if (MODE == 0 || MODE == 2) { sgr = Sg[row]; cstr = Cst[row]; }
            else br2 = bias[row];
            #pragma unroll
            for (int nt = 0; nt < 4; nt++) {
                #pragma unroll
                for (int e = 0; e < 2; e++) {
                    int pl = wn * 32 + nt * 8 + (lane & 3) * 2 + e;
                    int p = n0 + pl;
                    float v = acc[mt][nt][half * 2 + e];
                    if (MODE == 0) {
                        float mv = sst[0][0][pl], rv = sst[1][0][pl];
                        v = rv * v + (cstr - mv * rv * sgr);
                        if (row < 128)       O0[((size_t)u * 128 + row) * HW + p] = v;
                        else if (row < 256)  O1[((size_t)(u ^ 2) * 128 + (row - 128)) * HW + p] = v;
                        else                 O2[((size_t)(u ^ 2) * 128 + (row - 256)) * HW + p] = v;
                    } else if (MODE == 1) {
                        float res = ((u < 2 ? X1 : X2))[((size_t)(u & 1) * 128 + row) * HW + p];
                        size_t idx = ((size_t)u * 128 + row) * HW + p;
                        O0[idx] = v + br2 + res;
                    } else if (MODE == 2) {
                        float mv = sst[0][0][pl], rv = sst[1][0][pl];
                        v = rv * v + (cstr - mv * rv * sgr);
                        v = v / (1.f + __expf(-v));
                        O0[((size_t)u * 256 + row) * HW + p] = v;
                    } else if (MODE == 3) {
                        v += br2;
                        v = v / (1.f + __expf(-v));
                        size_t idx = ((size_t)u * 256 + row) * HW + p;
                        O0[idx] = O0[idx] + v;
                    } else {
                        v += br2;
                        size_t idx = ((size_t)u * 128 + row) * HW + p;
                        O0[idx] += v;
                    }
                }
            }
        }
    }
}

// ---------------- attention via tf32 MMA, lean smem (2 CTAs/SM) -------------
// Per-nt interleave: S slice (32x8) -> exp2 -> tiny staging -> P.V MMA.
#define KS_P 36
#define VS_P 40
#define PS_P 12
#define SM_KS 0
#define SM_VS (256*KS_P)
#define SM_PS (SM_VS + 256*VS_P)
#define SM_V2 (SM_PS + 8*32*PS_P)
#define SM_VSUM (SM_V2 + 256)
#define ATTN_SMEM ((SM_VSUM + 32) * 4)

__global__ void __launch_bounds__(256, 2)
attn_mma(const float* __restrict__ Q, const float* __restrict__ K,
         const float* __restrict__ V, float* __restrict__ O) {
    int blk = blockIdx.x;                  // b*256 + n*64 + h
    int h = blk & 63, n = (blk >> 6) & 3, b = blk >> 8;
    size_t base = ((size_t)(b * 128 + n * 32) * 64 + h) * 256;
    extern __shared__ float sm[];
    float* Ks = sm + SM_KS;
    float* Vs = sm + SM_VS;
    float* V2 = sm + SM_V2;
    float* Vsum = sm + SM_VSUM;
    int tid = threadIdx.x, lane = tid & 31, w = tid >> 5;
    float* Pw = sm + SM_PS + w * 32 * PS_P;

    #pragma unroll 4
    for (int dd = 0; dd < 32; dd++) {
        Ks[tid * KS_P + dd] = K[base + dd * HW + tid];
        Vs[tid * VS_P + dd] = V[base + dd * HW + tid];
    }
    __syncthreads();
    {
        float s = 0.f;
        #pragma unroll 8
        for (int jj = 0; jj < 32; jj++) s += Vs[(w * 32 + jj) * VS_P + lane];
        V2[w * 32 + lane] = s;
    }

    const float qs = 0.17677669529663687f * 1.4426950408889634f;
    int i0 = w * 32;
    uint32_t qa[2][4][4];
    #pragma unroll
    for (int mt = 0; mt < 2; mt++)
        #pragma unroll
        for (int kc = 0; kc < 4; kc++) {
            int r0 = i0 + mt * 16 + (lane >> 2);
            int c0 = kc * 8 + (lane & 3);
            qa[mt][kc][0] = __float_as_uint(Q[base + (size_t)c0 * HW + r0] * qs);
            qa[mt][kc][1] = __float_as_uint(Q[base + (size_t)c0 * HW + r0 + 8] * qs);
            qa[mt][kc][2] = __float_as_uint(Q[base + (size_t)(c0 + 4) * HW + r0] * qs);
            qa[mt][kc][3] = __float_as_uint(Q[base + (size_t)(c0 + 4) * HW + r0 + 8] * qs);
        }

    float l_run[2][2] = {{0.f, 0.f}, {0.f, 0.f}};
    float o[2][4][4];
    #pragma unroll
    for (int mt = 0; mt < 2; mt++)
        #pragma unroll
        for (int dt = 0; dt < 4; dt++)
            #pragma unroll
            for (int e = 0; e < 4; e++) o[mt][dt][e] = 0.f;

    for (int jb = 0; jb < 4; jb++) {
        int j0 = jb * 64;
        float rs_acc[2][2] = {{0.f, 0.f}, {0.f, 0.f}};
        #pragma unroll
        for (int nt = 0; nt < 8; nt++) {
            float s[2][4];
            #pragma unroll
            for (int mt = 0; mt < 2; mt++)
                #pragma unroll
                for (int e = 0; e < 4; e++) s[mt][e] = 0.f;
            #pragma unroll
            for (int kc = 0; kc < 4; kc++) {
                uint32_t bf[2];
                int jr = j0 + nt * 8 + (lane >> 2);
                int dc = kc * 8 + (lane & 3);
                bf[0] = __float_as_uint(Ks[jr * KS_P + dc]);
                bf[1] = __float_as_uint(Ks[jr * KS_P + dc + 4]);
                mma_tf32(s[0], qa[0][kc], bf);
                mma_tf32(s[1], qa[1][kc], bf);
            }
            // exp2 + stage P slice (32 rows x 8 cols per warp quadrant)
            #pragma unroll
            for (int mt = 0; mt < 2; mt++)
                #pragma unroll
                for (int hf = 0; hf < 2; hf++) {
                    int row = mt * 16 + (lane >> 2) + hf * 8;
                    float p0 = fexp2(s[mt][2 * hf]);
                    float p1 = fexp2(s[mt][2 * hf + 1]);
                    rs_acc[mt][hf] += p0 + p1;
                    Pw[row * PS_P + (lane & 3) * 2]     = p0;
                    Pw[row * PS_P + (lane & 3) * 2 + 1] = p1;
                }
            __syncwarp();
            uint32_t pa[2][4];
            #pragma unroll
            for (int mt = 0; mt < 2; mt++) {
                int r = mt * 16 + (lane >> 2);
                pa[mt][0] = __float_as_uint(Pw[r * PS_P + (lane & 3)]);
                pa[mt][1] = __float_as_uint(Pw[(r + 8) * PS_P + (lane & 3)]);
                pa[mt][2] = __float_as_uint(Pw[r * PS_P + (lane & 3) + 4]);
                pa[mt][3] = __float_as_uint(Pw[(r + 8) * PS_P + (lane & 3) + 4]);
            }
            uint32_t vb[4][2];
            #pragma unroll
            for (int dt = 0; dt < 4; dt++) {
                int jr = j0 + nt * 8 + (lane & 3);
                int dc = dt * 8 + (lane >> 2);
                vb[dt][0] = __float_as_uint(Vs[jr * VS_P + dc]);
                vb[dt][1] = __float_as_uint(Vs[(jr + 4) * VS_P + dc]);
            }
            #pragma unroll
            for (int mt = 0; mt < 2; mt++)
                #pragma unroll
                for (int dt = 0; dt < 4; dt++)
                    mma_tf32(o[mt][dt], pa[mt], vb[dt]);
            __syncwarp();
        }
        #pragma unroll
        for (int mt = 0; mt < 2; mt++)
            #pragma unroll
            for (int hf = 0; hf < 2; hf++) {
                float rs = rs_acc[mt][hf];
                rs += __shfl_xor_sync(0xffffffffu, rs, 1);
                rs += __shfl_xor_sync(0xffffffffu, rs, 2);
                l_run[mt][hf] += rs;
            }
    }

    // epilogue: stage normalized O through the (now free) Ks region
    __syncthreads();
    float* Ow = Ks + w * 32 * 36;
    #pragma unroll
    for (int mt = 0; mt < 2; mt++)
        #pragma unroll
        for (int hf = 0; hf < 2; hf++) {
            float inv = 1.f / l_run[mt][hf];
            int row = mt * 16 + (lane >> 2) + hf * 8;
            #pragma unroll
            for (int dt = 0; dt < 4; dt++) {
                Ow[row * 36 + dt * 8 + (lane & 3) * 2]     = o[mt][dt][2 * hf] * inv;
                Ow[row * 36 + dt * 8 + (lane & 3) * 2 + 1] = o[mt][dt][2 * hf + 1] * inv;
            }
        }
    if (tid < 32) {
        float s = 0.f;
        #pragma unroll
        for (int ww = 0; ww < 8; ww++) s += V2[ww * 32 + tid];
        Vsum[tid] = s;
    }
    __syncthreads();
    const float eps = 1e-6f;
    const float norm = 1.f / (1.f + 256.f * eps);
    #pragma unroll 4
    for (int d = 0; d < 32; d++) {
        float val = (Ow[lane * 36 + d] + eps * Vsum[d]) * norm;
        O[base + (size_t)d * HW + i0 + lane] = val;
    }
}

// ---------------- depthwise 3x3 / 5x5 / 7x7 (SAME, zero pad), 8x64 tiles ----
__global__ void dw_kernel(const float* __restrict__ Y,
                          const float* __restrict__ w3, const float* __restrict__ b3,
                          const float* __restrict__ w5, const float* __restrict__ b5,
                          const float* __restrict__ w7, const float* __restrict__ b7,
                          float* __restrict__ F) {
    __shared__ float S[14][70];
    __shared__ float wgt[84];
    int z = blockIdx.z; int ch = z & 255; int u = z >> 8;
    int w0 = blockIdx.x * 64, h0 = blockIdx.y * 8;
    int tid = threadIdx.x;
    if (tid < 9)       wgt[tid] = w3[ch * 9 + tid];
    else if (tid < 34) wgt[tid] = w5[ch * 25 + tid - 9];
    else if (tid < 83) wgt[tid] = w7[ch * 49 + tid - 34];
    const float* Yp = Y + ((size_t)u * 256 + ch) * HW;
    for (int i = tid; i < 980; i += 256) {
        int r = i / 70, c = i % 70;
        int gh = h0 - 3 + r, gw = w0 - 3 + c;
        float v = 0.f;
        if ((unsigned)gh < 64u && (unsigned)gw < 256u) v = Yp[gh * 256 + gw];
        S[r][c] = v;
    }
    __syncthreads();
    int tx = tid & 63, ty = tid >> 6;
    float bb3 = b3[ch], bb5 = b5[ch], bb7 = b7[ch];
    #pragma unroll
    for (int rr = 0; rr < 2; rr++) {
        int rc = ty + rr * 4 + 3, cc = tx + 3;
        float f3 = bb3, f5 = bb5, f7 = bb7;
        #pragma unroll
        for (int dy = -3; dy <= 3; dy++)
            #pragma unroll
            for (int dx = -3; dx <= 3; dx++) {
                float v = S[rc + dy][cc + dx];
                f7 += v * wgt[34 + (dy + 3) * 7 + (dx + 3)];
                if (dy >= -2 && dy <= 2 && dx >= -2 && dx <= 2)
                    f5 += v * wgt[9 + (dy + 2) * 5 + (dx + 2)];
                if (dy >= -1 && dy <= 1 && dx >= -1 && dx <= 1)
                    f3 += v * wgt[(dy + 1) * 3 + (dx + 1)];
            }
        size_t pix = (size_t)(h0 + ty + rr * 4) * 256 + (w0 + tx);
        size_t ob = (size_t)u * 768 * HW + pix;
        F[ob + (size_t) ch        * HW] = f3;
        F[ob + (size_t)(256 + ch) * HW] = f5;
        F[ob + (size_t)(512 + ch) * HW] = f7;
    }
}

// ---------------- host launcher --------------------------------------------
extern "C" void kernel_launch(void* const* d_in, const int* in_sizes, int n_in,
                              void* d_out, int out_size) {
    const float* feats1 = (const float*)d_in[0];
    const float* feats2 = (const float*)d_in[1];
    const float* an_g  = (const float*)d_in[2];
    const float* an_b  = (const float*)d_in[3];
    const float* anc_g = (const float*)d_in[4];
    const float* anc_b = (const float*)d_in[5];
    const float* wq    = (const float*)d_in[6];
    const float* bq    = (const float*)d_in[7];
    const float* wkv   = (const float*)d_in[8];
    const float* bkv   = (const float*)d_in[9];
    const float* wo    = (const float*)d_in[10];
    const float* bo    = (const float*)d_in[11];
    const float* fn_g  = (const float*)d_in[12];
    const float* fn_b  = (const float*)d_in[13];
    const float* w_in  = (const float*)d_in[14];
    const float* b_in  = (const float*)d_in[15];
    const float* w_dw3 = (const float*)d_in[16];
    const float* b_dw3 = (const float*)d_in[17];
    const float* w_dw5 = (const float*)d_in[18];
    const float* b_dw5 = (const float*)d_in[19];
    const float* w_dw7 = (const float*)d_in[20];
    const float* b_dw7 = (const float*)d_in[21];
    const float* w_pw  = (const float*)d_in[22];
    const float* b_pw  = (const float*)d_in[23];
    const float* w_out = (const float*)d_in[24];
    const float* b_out = (const float*)d_in[25];
    float* dout = (float*)d_out;

    float *Q, *K, *V, *O, *Y, *F, *WA, *SgA, *CA, *WIN, *SgI, *CI;
    cudaGetSymbolAddress((void**)&Q,  g_Qb);
    cudaGetSymbolAddress((void**)&K,  g_Kb);
    cudaGetSymbolAddress((void**)&V,  g_Vb);
    cudaGetSymbolAddress((void**)&O,  g_Ob);
    cudaGetSymbolAddress((void**)&Y,  g_Y);
    cudaGetSymbolAddress((void**)&F,  g_F);
    cudaGetSymbolAddress((void**)&WA, g_WA);
    cudaGetSymbolAddress((void**)&SgA, g_SgA);
    cudaGetSymbolAddress((void**)&CA, g_CA);
    cudaGetSymbolAddress((void**)&WIN, g_WIN);
    cudaGetSymbolAddress((void**)&SgI, g_SgI);
    cudaGetSymbolAddress((void**)&CI, g_CI);

    const int smA = 3 * (128 * 20 + 16 * 136) * 4;   // BM=128/BN=128
    const int smB = 3 * (256 * 20 + 16 * 72)  * 4;   // BM=256/BN=64
    cudaFuncSetAttribute((const void*)gemm_tc<128, 0, 128, 128>, cudaFuncAttributeMaxDynamicSharedMemorySize, smA);
    cudaFuncSetAttribute((const void*)gemm_tc<128, 1, 128, 128>, cudaFuncAttributeMaxDynamicSharedMemorySize, smA);
    cudaFuncSetAttribute((const void*)gemm_tc<128, 2, 256, 64>,  cudaFuncAttributeMaxDynamicSharedMemorySize, smB);
    cudaFuncSetAttribute((const void*)gemm_tc<768, 3, 256, 64>,  cudaFuncAttributeMaxDynamicSharedMemorySize, smB);
    cudaFuncSetAttribute((const void*)gemm_tc<256, 4, 128, 128>, cudaFuncAttributeMaxDynamicSharedMemorySize, smA);
    cudaFuncSetAttribute((const void*)attn_mma, cudaFuncAttributeMaxDynamicSharedMemorySize, ATTN_SMEM);

    // 1. weight prep
    prep_kernel<<<640, 128>>>(wq, bq, wkv, bkv, an_g, an_b, anc_g, anc_b,
                              w_in, b_in, fn_g, fn_b);
    // 2. fused LN(in-kernel stats) + q/kv projection
    gemm_tc<128, 0, 128, 128><<<dim3(128, 3, 4), 256, smA>>>(WA, nullptr, Q, K, V, SgA, CA,
                                                             feats1, feats2, nullptr, 1e-6f);
    // 3. attention (tf32 MMA flash, lean smem)
    attn_mma<<<1024, 256, ATTN_SMEM>>>(Q, K, V, O);
    // 4. output projection + residual(feats) -> d_out
    gemm_tc<128, 1, 128, 128><<<dim3(128, 1, 4), 256, smA>>>(wo, O, dout, nullptr, nullptr,
                                                             nullptr, nullptr,
                                                             feats1, feats2, bo, 0.f);
    // 5. fused LN(in-kernel stats) + w_in + SiLU -> Y
    gemm_tc<128, 2, 256, 64><<<dim3(256, 1, 4), 256, smB>>>(WIN, dout, Y, nullptr, nullptr,
                                                            SgI, CI, nullptr, nullptr, nullptr, 1e-5f);
    // 6. depthwise 3/5/7 -> F (768 channels)
    dw_kernel<<<dim3(4, 8, 1024), 256>>>(Y, w_dw3, b_dw3, w_dw5, b_dw5, w_dw7, b_dw7, F);
    // 7. pointwise GEMM (K=768) + SiLU + residual into Y
    gemm_tc<768, 3, 256, 64><<<dim3(256, 1, 4), 256, smB>>>(w_pw, F, Y, nullptr, nullptr,
                                                            nullptr, nullptr, nullptr, nullptr, b_pw, 0.f);
    // 8. w_out GEMM (K=256), accumulate into d_out
    gemm_tc<256, 4, 128, 128><<<dim3(128, 1, 4), 256, smA>>>(w_out, Y, dout, nullptr, nullptr,
                                                             nullptr, nullptr, nullptr, nullptr, b_out, 0.f);
}

// round 10
// speedup vs baseline: 1.1714x; 1.0054x over previous
#include <cuda_runtime.h>
#include <cuda_fp16.h>
#include <math.h>
#include <stdint.h>

#define HW 16384          // 64*256 pixels per (batch, channel) plane

// ---------------- scratch (static device globals; no allocation allowed) ----
__device__ float g_Qb[4*128*HW];
__device__ float g_Kb[4*128*HW];
__device__ float g_Vb[4*128*HW];
__device__ float g_Ob[4*128*HW];
__device__ float g_Y [4*256*HW];
__device__ __half g_Fh[(size_t)4*768*HW];
__device__ __half g_WPWh[256*768];
__device__ float g_WA [384*128], g_SgA[384], g_CA[384];
__device__ float g_WIN[256*128], g_SgI[256], g_CI[256];

// ---------------- small helpers --------------------------------------------
__device__ __forceinline__ uint32_t smem_u32(const void* p) {
    return (uint32_t)__cvta_generic_to_shared(p);
}
__device__ __forceinline__ void cp16(uint32_t dst, const void* src) {
    asm volatile("cp.async.cg.shared.global [%0], [%1], 16;\n" :: "r"(dst), "l"(src));
}
__device__ __forceinline__ void cp_commit() { asm volatile("cp.async.commit_group;\n"); }
__device__ __forceinline__ void cp_wait1()  { asm volatile("cp.async.wait_group 1;\n"); }

__device__ __forceinline__ void mma_tf32(float* c, const uint32_t* a, const uint32_t* b) {
    asm volatile("mma.sync.aligned.m16n8k8.row.col.f32.tf32.tf32.f32 "
        "{%0,%1,%2,%3}, {%4,%5,%6,%7}, {%8,%9}, {%0,%1,%2,%3};"
        : "+f"(c[0]), "+f"(c[1]), "+f"(c[2]), "+f"(c[3])
        : "r"(a[0]), "r"(a[1]), "r"(a[2]), "r"(a[3]), "r"(b[0]), "r"(b[1]));
}
__device__ __forceinline__ void mma_f16(float* c, const uint32_t* a, const uint32_t* b) {
    asm volatile("mma.sync.aligned.m16n8k16.row.col.f32.f16.f16.f32 "
        "{%0,%1,%2,%3}, {%4,%5,%6,%7}, {%8,%9}, {%0,%1,%2,%3};"
        : "+f"(c[0]), "+f"(c[1]), "+f"(c[2]), "+f"(c[3])
        : "r"(a[0]), "r"(a[1]), "r"(a[2]), "r"(a[3]), "r"(b[0]), "r"(b[1]));
}
__device__ __forceinline__ void ldsm4(uint32_t* r, uint32_t addr) {
    asm volatile("ldmatrix.sync.aligned.m8n8.x4.shared.b16 {%0,%1,%2,%3}, [%4];"
        : "=r"(r[0]), "=r"(r[1]), "=r"(r[2]), "=r"(r[3]) : "r"(addr));
}
__device__ __forceinline__ void ldsm2t(uint32_t* r, uint32_t addr) {
    asm volatile("ldmatrix.sync.aligned.m8n8.x2.trans.shared.b16 {%0,%1}, [%2];"
        : "=r"(r[0]), "=r"(r[1]) : "r"(addr));
}
__device__ __forceinline__ float fexp2(float x) {
    float r; asm("ex2.approx.ftz.f32 %0, %1;" : "=f"(r) : "f"(x)); return r;
}

// ---------------- fold LN gamma/beta into GEMM weights ---------------------
__global__ void prep_kernel(const float* __restrict__ wq,  const float* __restrict__ bq,
                            const float* __restrict__ wkv, const float* __restrict__ bkv,
                            const float* __restrict__ an_g, const float* __restrict__ an_b,
                            const float* __restrict__ anc_g, const float* __restrict__ anc_b,
                            const float* __restrict__ w_in, const float* __restrict__ b_in,
                            const float* __restrict__ fn_g, const float* __restrict__ fn_b) {
    int r = blockIdx.x, t = threadIdx.x;   // 640 blocks x 128 threads
    __shared__ float red[2][4];
    float wl, gg, bb, extra;
    float *Wdst, *Sgd, *Cd;
    if (r < 128)      { wl = wq [r*128 + t];        gg = an_g[t];  bb = an_b[t];  extra = bq [r];
                        Wdst = g_WA  + r*128;        Sgd = g_SgA + r;  Cd = g_CA + r; }
    else if (r < 384) { int rr = r - 128;
                        wl = wkv[rr*128 + t];       gg = anc_g[t]; bb = anc_b[t]; extra = bkv[rr];
                        Wdst = g_WA  + r*128;        Sgd = g_SgA + r;  Cd = g_CA + r; }
    else              { int rr = r - 384;
                        wl = w_in[rr*128 + t];      gg = fn_g[t];  bb = fn_b[t];  extra = b_in[rr];
                        Wdst = g_WIN + rr*128;       Sgd = g_SgI + rr; Cd = g_CI + rr; }
    float wg = wl * gg;
    Wdst[t] = wg;
    float s1 = wg, s2 = wl * bb;
    #pragma unroll
    for (int off = 16; off; off >>= 1) {
        s1 += __shfl_down_sync(0xffffffffu, s1, off);
        s2 += __shfl_down_sync(0xffffffffu, s2, off);
    }
    if ((t & 31) == 0) { red[0][t >> 5] = s1; red[1][t >> 5] = s2; }
    __syncthreads();
    if (t == 0) {
        float a = red[0][0] + red[0][1] + red[0][2] + red[0][3];
        float b = red[1][0] + red[1][1] + red[1][2] + red[1][3];
        *Sgd = a; *Cd = b + extra;
    }
}

// ---------------- convert w_pw to fp16 --------------------------------------
__global__ void convh_kernel(const float* __restrict__ W, __half* __restrict__ Wh, int n) {
    int i = blockIdx.x * 256 + threadIdx.x;
    if (i < n) Wh[i] = __float2half(W[i]);
}

// ---------------- tf32 tensor-core GEMM (proven config) ---------------------
template<int K, int MODE, int BM, int BN>
__global__ void __launch_bounds__(256)
gemm_tc(const float* __restrict__ A, const float* __restrict__ B,
        float* __restrict__ O0, float* __restrict__ O1, float* __restrict__ O2,
        const float* __restrict__ Sg, const float* __restrict__ Cst,
        const float* __restrict__ X1, const float* __restrict__ X2,
        const float* __restrict__ bias, float eps) {
    constexpr int BK = 16, ST = 3;
    constexpr int KT = K / BK;
    constexpr int ASP = 20;
    constexpr int BSP = BN + 8;
    constexpr int ASZ = BM * ASP;
    constexpr int BSZ = BK * BSP;
    constexpr int NA = BM / 64;
    constexpr int NB = BN / 64;
    constexpr int WN = (BM == 128) ? 4 : 2;
    constexpr bool STATS = (MODE == 0 || MODE == 2);
    constexpr int SH = (BN == 64) ? 4 : 2;
    constexpr int RT = 16 / SH;
    extern __shared__ float smf[];
    float* As = smf;
    float* Bs = smf + ST * ASZ;
    __shared__ float sst[STATS ? 2 : 1][STATS ? SH : 1][STATS ? BN : 1];

    int tid = threadIdx.x, lane = tid & 31, wid = tid >> 5;
    int wm = wid / WN, wn = wid % WN;
    int n0 = blockIdx.x * BN, m0 = blockIdx.y * BM, u = blockIdx.z;
    const float* Ap = A + (size_t)m0 * K;
    const float* Bp;
    if (MODE == 0) Bp = (u < 2 ? X1 : X2) + (size_t)(u & 1) * 128 * HW + n0;
    else           Bp = B + (size_t)u * K * HW + n0;

    float acc[4][4][4];
    #pragma unroll
    for (int i = 0; i < 4; i++)
        #pragma unroll
        for (int j = 0; j < 4; j++)
            #pragma unroll
            for (int e = 0; e < 4; e++) acc[i][j][e] = 0.f;

    int ar[NA], ac[NA], br[NB], bc[NB];
    #pragma unroll
    for (int i = 0; i < NA; i++) {
        int idx = tid + i * 256;
        ar[i] = idx >> 2; ac[i] = (idx & 3) << 2;
    }
    #pragma unroll
    for (int i = 0; i < NB; i++) {
        int idx = tid + i * 256;
        br[i] = idx / (BN / 4); bc[i] = (idx % (BN / 4)) << 2;
    }
    int sc = tid % BN, sg = tid / BN;
    float s_sum = 0.f, s_sq = 0.f;
    int lm = lane >> 3;
    int loff = (((lane & 7) + (lm & 1) * 8)) * ASP + (lm >> 1) * 4;
    uint32_t as_base = smem_u32(As);

    #define PREFETCH(sidx, k0)                                                     \
        {   _Pragma("unroll")                                                      \
            for (int i = 0; i < NA; i++)                                           \
                cp16(smem_u32(&As[(sidx) * ASZ + ar[i] * ASP + ac[i]]),            \
                     Ap + (size_t)ar[i] * K + (k0) + ac[i]);                       \
            _Pragma("unroll")                                                      \
            for (int i = 0; i < NB; i++)                                           \
                cp16(smem_u32(&Bs[(sidx) * BSZ + br[i] * BSP + bc[i]]),            \
                     Bp + (size_t)((k0) + br[i]) * HW + bc[i]);                    \
        }

    PREFETCH(0, 0); cp_commit();
    if (KT > 1) PREFETCH(1, BK);
    cp_commit();

    for (int kt = 0; kt < KT; kt++) {
        cp_wait1();
        __syncthreads();
        int st = kt % ST;
        const float* bs = Bs + st * BSZ;
        if (STATS) {
            #pragma unroll
            for (int rr = 0; rr < RT; rr++) {
                float v = bs[(sg * RT + rr) * BSP + sc];
                s_sum += v; s_sq += v * v;
            }
        }
        uint32_t abase = as_base + (uint32_t)(st * ASZ + wm * 64 * ASP + loff) * 4;
        #pragma unroll
        for (int s8 = 0; s8 < 2; s8++) {
            uint32_t a[4][4], b[4][2];
            #pragma unroll
            for (int mt = 0; mt < 4; mt++)
                ldsm4(a[mt], abase + (uint32_t)(mt * 16 * ASP + s8 * 8) * 4);
            #pragma unroll
            for (int nt = 0; nt < 4; nt++) {
                const float* bp = bs + (s8 * 8 + (lane & 3)) * BSP
                                     + wn * 32 + nt * 8 + (lane >> 2);
                b[nt][0] = __float_as_uint(bp[0]);
                b[nt][1] = __float_as_uint(bp[4 * BSP]);
            }
            #pragma unroll
            for (int mt = 0; mt < 4; mt++)
                #pragma unroll
                for (int nt = 0; nt < 4; nt++)
                    mma_tf32(acc[mt][nt], a[mt], b[nt]);
        }
        if (kt + 2 < KT) PREFETCH((kt + 2) % ST, (kt + 2) * BK);
        cp_commit();
    }
    #undef PREFETCH

    if (STATS) {
        sst[0][sg][sc] = s_sum;
        sst[1][sg][sc] = s_sq;
        __syncthreads();
        if (tid < BN) {
            float S = 0.f, SS = 0.f;
            #pragma unroll
            for (int g = 0; g < SH; g++) { S += sst[0][g][tid]; SS += sst[1][g][tid]; }
            float m = S * (1.f / 128.f);
            float var = SS * (1.f / 128.f) - m * m;
            sst[0][0][tid] = m;
            sst[1][0][tid] = rsqrtf(var + eps);
        }
        __syncthreads();
    }

    #pragma unroll
    for (int mt = 0; mt < 4; mt++) {
        #pragma unroll
        for (int half = 0; half < 2; half++) {
            int row = m0 + wm * 64 + mt * 16 + (lane >> 2) + half * 8;
            float sgr = 0.f, cstr = 0.f, br2 = 0.f;
            if (MODE == 0 || MODE == 2) { sgr = Sg[row]; cstr = Cst[row]; }
            else br2 = bias[row];
            #pragma unroll
            for (int nt = 0; nt < 4; nt++) {
                #pragma unroll
                for (int e = 0; e < 2; e++) {
                    int pl = wn * 32 + nt * 8 + (lane & 3) * 2 + e;
                    int p = n0 + pl;
                    float v = acc[mt][nt][half * 2 + e];
                    if (MODE == 0) {
                        float mv = sst[0][0][pl], rv = sst[1][0][pl];
                        v = rv * v + (cstr - mv * rv * sgr);
                        if (row < 128)       O0[((size_t)u * 128 + row) * HW + p] = v;
                        else if (row < 256)  O1[((size_t)(u ^ 2) * 128 + (row - 128)) * HW + p] = v;
                        else                 O2[((size_t)(u ^ 2) * 128 + (row - 256)) * HW + p] = v;
                    } else if (MODE == 1) {
                        float res = ((u < 2 ? X1 : X2))[((size_t)(u & 1) * 128 + row) * HW + p];
                        size_t idx = ((size_t)u * 128 + row) * HW + p;
                        O0[idx] = v + br2 + res;
                    } else if (MODE == 2) {
                        float mv = sst[0][0][pl], rv = sst[1][0][pl];
                        v = rv * v + (cstr - mv * rv * sgr);
                        v = v / (1.f + __expf(-v));
                        O0[((size_t)u * 256 + row) * HW + p] = v;
                    } else {
                        v += br2;
                        size_t idx = ((size_t)u * 128 + row) * HW + p;
                        O0[idx] += v;
                    }
                }
            }
        }
    }
}

// ---------------- fp16 GEMM for the pointwise conv --------------------------
// A: g_WPWh [256][768] half, B: g_Fh [4][768][HW] half.
// BM=256, BN=64, BK=32, 8 warps 4x2, warp tile 64x32, m16n8k16.
__global__ void __launch_bounds__(256)
gemm_pw_f16(const __half* __restrict__ A, const __half* __restrict__ B,
            float* __restrict__ Y, const float* __restrict__ bias) {
    constexpr int K = 768, BN = 64, BK = 32, ST = 3;
    constexpr int KT = K / BK;           // 24
    constexpr int ASPH = 40;             // A pitch (halves)
    constexpr int BSPH = BN + 8;         // 72
    constexpr int ASZ = 256 * ASPH;
    constexpr int BSZ = BK * BSPH;
    extern __shared__ __half smh[];
    __half* As = smh;
    __half* Bs = smh + ST * ASZ;

    int tid = threadIdx.x, lane = tid & 31, wid = tid >> 5;
    int wm = wid >> 1, wn = wid & 1;
    int n0 = blockIdx.x * BN, u = blockIdx.z;
    const __half* Bp = B + (size_t)u * K * HW + n0;

    float acc[4][4][4];
    #pragma unroll
    for (int i = 0; i < 4; i++)
        #pragma unroll
        for (int j = 0; j < 4; j++)
            #pragma unroll
            for (int e = 0; e < 4; e++) acc[i][j][e] = 0.f;

    // A: 4 float4/thread (1024 total = 256 rows x 4 segs of 8 halves)
    int aro[4], aco[4];
    #pragma unroll
    for (int i = 0; i < 4; i++) {
        int idx = tid + i * 256;
        aro[i] = idx >> 2; aco[i] = (idx & 3) << 3;
    }
    // B: 1 float4/thread (256 = 32 rows x 8 segs)
    int brw = tid >> 3, bcl = (tid & 7) << 3;

    int arow_l = lane & 15, acol_l = (lane >> 4) << 3;                 // A x4
    int brow_l = (lane & 7) + ((lane >> 3) & 1) * 8;                   // B x2.trans
    uint32_t as_base = smem_u32(As);
    uint32_t bs_base = smem_u32(Bs);

    #define PF16(sidx, k0)                                                         \
        {   _Pragma("unroll")                                                      \
            for (int i = 0; i < 4; i++)                                            \
                cp16(smem_u32(&As[(sidx) * ASZ + aro[i] * ASPH + aco[i]]),         \
                     A + (size_t)aro[i] * K + (k0) + aco[i]);                      \
            cp16(smem_u32(&Bs[(sidx) * BSZ + brw * BSPH + bcl]),                   \
                 Bp + (size_t)((k0) + brw) * HW + bcl);                            \
        }

    PF16(0, 0); cp_commit();
    PF16(1, BK); cp_commit();

    for (int kt = 0; kt < KT; kt++) {
        cp_wait1();
        __syncthreads();
        int st = kt % ST;
        uint32_t abase = as_base + (uint32_t)(st * ASZ + (wm * 64 + arow_l) * ASPH + acol_l) * 2;
        uint32_t bbase = bs_base + (uint32_t)(st * BSZ + brow_l * BSPH + wn * 32) * 2;
        #pragma unroll
        for (int s16 = 0; s16 < 2; s16++) {
            uint32_t a[4][4], b[4][2];
            #pragma unroll
            for (int mt = 0; mt < 4; mt++)
                ldsm4(a[mt], abase + (uint32_t)(mt * 16 * ASPH + s16 * 16) * 2);
            #pragma unroll
            for (int nt = 0; nt < 4; nt++)
                ldsm2t(b[nt], bbase + (uint32_t)(s16 * 16 * BSPH + nt * 8) * 2);
            #pragma unroll
            for (int mt = 0; mt < 4; mt++)
                #pragma unroll
                for (int nt = 0; nt < 4; nt++)
                    mma_f16(acc[mt][nt], a[mt], b[nt]);
        }
        if (kt + 2 < KT) PF16((kt + 2) % ST, (kt + 2) * BK);
        cp_commit();
    }
    #undef PF16

    // epilogue: bias + SiLU, Y +=
    #pragma unroll
    for (int mt = 0; mt < 4; mt++) {
        #pragma unroll
        for (int half = 0; half < 2; half++) {
            int row = wm * 64 + mt * 16 + (lane >> 2) + half * 8;
            float br2 = bias[row];
            #pragma unroll
            for (int nt = 0; nt < 4; nt++) {
                #pragma unroll
                for (int e = 0; e < 2; e++) {
                    int p = n0 + wn * 32 + nt * 8 + (lane & 3) * 2 + e;
                    float v = acc[mt][nt][half * 2 + e] + br2;
                    v = v / (1.f + __expf(-v));
                    size_t idx = ((size_t)u * 256 + row) * HW + p;
                    Y[idx] = Y[idx] + v;
                }
            }
        }
    }
}

// ---------------- attention via tf32 MMA, lean smem (2 CTAs/SM) -------------
#define KS_P 36
#define VS_P 40
#define PS_P 12
#define SM_KS 0
#define SM_VS (256*KS_P)
#define SM_PS (SM_VS + 256*VS_P)
#define SM_V2 (SM_PS + 8*32*PS_P)
#define SM_VSUM (SM_V2 + 256)
#define ATTN_SMEM ((SM_VSUM + 32) * 4)

__global__ void __launch_bounds__(256, 2)
attn_mma(const float* __restrict__ Q, const float* __restrict__ K,
         const float* __restrict__ V, float* __restrict__ O) {
    int blk = blockIdx.x;                  // b*256 + n*64 + h
    int h = blk & 63, n = (blk >> 6) & 3, b = blk >> 8;
    size_t base = ((size_t)(b * 128 + n * 32) * 64 + h) * 256;
    extern __shared__ float sm[];
    float* Ks = sm + SM_KS;
    float* Vs = sm + SM_VS;
    float* V2 = sm + SM_V2;
    float* Vsum = sm + SM_VSUM;
    int tid = threadIdx.x, lane = tid & 31, w = tid >> 5;
    float* Pw = sm + SM_PS + w * 32 * PS_P;

    #pragma unroll 4
    for (int dd = 0; dd < 32; dd++) {
        Ks[tid * KS_P + dd] = K[base + dd * HW + tid];
        Vs[tid * VS_P + dd] = V[base + dd * HW + tid];
    }
    __syncthreads();
    {
        float s = 0.f;
        #pragma unroll 8
        for (int jj = 0; jj < 32; jj++) s += Vs[(w * 32 + jj) * VS_P + lane];
        V2[w * 32 + lane] = s;
    }

    const float qs = 0.17677669529663687f * 1.4426950408889634f;
    int i0 = w * 32;
    uint32_t qa[2][4][4];
    #pragma unroll
    for (int mt = 0; mt < 2; mt++)
        #pragma unroll
        for (int kc = 0; kc < 4; kc++) {
            int r0 = i0 + mt * 16 + (lane >> 2);
            int c0 = kc * 8 + (lane & 3);
            qa[mt][kc][0] = __float_as_uint(Q[base + (size_t)c0 * HW + r0] * qs);
            qa[mt][kc][1] = __float_as_uint(Q[base + (size_t)c0 * HW + r0 + 8] * qs);
            qa[mt][kc][2] = __float_as_uint(Q[base + (size_t)(c0 + 4) * HW + r0] * qs);
            qa[mt][kc][3] = __float_as_uint(Q[base + (size_t)(c0 + 4) * HW + r0 + 8] * qs);
        }

    float l_run[2][2] = {{0.f, 0.f}, {0.f, 0.f}};
    float o[2][4][4];
    #pragma unroll
    for (int mt = 0; mt < 2; mt++)
        #pragma unroll
        for (int dt = 0; dt < 4; dt++)
            #pragma unroll
            for (int e = 0; e < 4; e++) o[mt][dt][e] = 0.f;

    for (int jb = 0; jb < 4; jb++) {
        int j0 = jb * 64;
        float rs_acc[2][2] = {{0.f, 0.f}, {0.f, 0.f}};
        #pragma unroll
        for (int nt = 0; nt < 8; nt++) {
            float s[2][4];
            #pragma unroll
            for (int mt = 0; mt < 2; mt++)
                #pragma unroll
                for (int e = 0; e < 4; e++) s[mt][e] = 0.f;
            #pragma unroll
            for (int kc = 0; kc < 4; kc++) {
                uint32_t bf[2];
                int jr = j0 + nt * 8 + (lane >> 2);
                int dc = kc * 8 + (lane & 3);
                bf[0] = __float_as_uint(Ks[jr * KS_P + dc]);
                bf[1] = __float_as_uint(Ks[jr * KS_P + dc + 4]);
                mma_tf32(s[0], qa[0][kc], bf);
                mma_tf32(s[1], qa[1][kc], bf);
            }
            #pragma unroll
            for (int mt = 0; mt < 2; mt++)
                #pragma unroll
                for (int hf = 0; hf < 2; hf++) {
                    int row = mt * 16 + (lane >> 2) + hf * 8;
                    float p0 = fexp2(s[mt][2 * hf]);
                    float p1 = fexp2(s[mt][2 * hf + 1]);
                    rs_acc[mt][hf] += p0 + p1;
                    Pw[row * PS_P + (lane & 3) * 2]     = p0;
                    Pw[row * PS_P + (lane & 3) * 2 + 1] = p1;
                }
            __syncwarp();
            uint32_t pa[2][4];
            #pragma unroll
            for (int mt = 0; mt < 2; mt++) {
                int r = mt * 16 + (lane >> 2);
                pa[mt][0] = __float_as_uint(Pw[r * PS_P + (lane & 3)]);
                pa[mt][1] = __float_as_uint(Pw[(r + 8) * PS_P + (lane & 3)]);
                pa[mt][2] = __float_as_uint(Pw[r * PS_P + (lane & 3) + 4]);
                pa[mt][3] = __float_as_uint(Pw[(r + 8) * PS_P + (lane & 3) + 4]);
            }
            uint32_t vb[4][2];
            #pragma unroll
            for (int dt = 0; dt < 4; dt++) {
                int jr = j0 + nt * 8 + (lane & 3);
                int dc = dt * 8 + (lane >> 2);
                vb[dt][0] = __float_as_uint(Vs[jr * VS_P + dc]);
                vb[dt][1] = __float_as_uint(Vs[(jr + 4) * VS_P + dc]);
            }
            #pragma unroll
            for (int mt = 0; mt < 2; mt++)
                #pragma unroll
                for (int dt = 0; dt < 4; dt++)
                    mma_tf32(o[mt][dt], pa[mt], vb[dt]);
            __syncwarp();
        }
        #pragma unroll
        for (int mt = 0; mt < 2; mt++)
            #pragma unroll
            for (int hf = 0; hf < 2; hf++) {
                float rs = rs_acc[mt][hf];
                rs += __shfl_xor_sync(0xffffffffu, rs, 1);
                rs += __shfl_xor_sync(0xffffffffu, rs, 2);
                l_run[mt][hf] += rs;
            }
    }

    __syncthreads();
    float* Ow = Ks + w * 32 * 36;
    #pragma unroll
    for (int mt = 0; mt < 2; mt++)
        #pragma unroll
        for (int hf = 0; hf < 2; hf++) {
            float inv = 1.f / l_run[mt][hf];
            int row = mt * 16 + (lane >> 2) + hf * 8;
            #pragma unroll
            for (int dt = 0; dt < 4; dt++) {
                Ow[row * 36 + dt * 8 + (lane & 3) * 2]     = o[mt][dt][2 * hf] * inv;
                Ow[row * 36 + dt * 8 + (lane & 3) * 2 + 1] = o[mt][dt][2 * hf + 1] * inv;
            }
        }
    if (tid < 32) {
        float s = 0.f;
        #pragma unroll
        for (int ww = 0; ww < 8; ww++) s += V2[ww * 32 + tid];
        Vsum[tid] = s;
    }
    __syncthreads();
    const float eps = 1e-6f;
    const float norm = 1.f / (1.f + 256.f * eps);
    #pragma unroll 4
    for (int d = 0; d < 32; d++) {
        float val = (Ow[lane * 36 + d] + eps * Vsum[d]) * norm;
        O[base + (size_t)d * HW + i0 + lane] = val;
    }
}

// ---------------- depthwise 3x3 / 5x5 / 7x7 -> half F -----------------------
__global__ void dw_kernel(const float* __restrict__ Y,
                          const float* __restrict__ w3, const float* __restrict__ b3,
                          const float* __restrict__ w5, const float* __restrict__ b5,
                          const float* __restrict__ w7, const float* __restrict__ b7,
                          __half* __restrict__ F) {
    __shared__ float S[14][70];
    __shared__ float wgt[84];
    int z = blockIdx.z; int ch = z & 255; int u = z >> 8;
    int w0 = blockIdx.x * 64, h0 = blockIdx.y * 8;
    int tid = threadIdx.x;
    if (tid < 9)       wgt[tid] = w3[ch * 9 + tid];
    else if (tid < 34) wgt[tid] = w5[ch * 25 + tid - 9];
    else if (tid < 83) wgt[tid] = w7[ch * 49 + tid - 34];
    const float* Yp = Y + ((size_t)u * 256 + ch) * HW;
    for (int i = tid; i < 980; i += 256) {
        int r = i / 70, c = i % 70;
        int gh = h0 - 3 + r, gw = w0 - 3 + c;
        float v = 0.f;
        if ((unsigned)gh < 64u && (unsigned)gw < 256u) v = Yp[gh * 256 + gw];
        S[r][c] = v;
    }
    __syncthreads();
    int tx = tid & 63, ty = tid >> 6;
    float bb3 = b3[ch], bb5 = b5[ch], bb7 = b7[ch];
    #pragma unroll
    for (int rr = 0; rr < 2; rr++) {
        int rc = ty + rr * 4 + 3, cc = tx + 3;
        float f3 = bb3, f5 = bb5, f7 = bb7;
        #pragma unroll
        for (int dy = -3; dy <= 3; dy++)
            #pragma unroll
            for (int dx = -3; dx <= 3; dx++) {
                float v = S[rc + dy][cc + dx];
                f7 += v * wgt[34 + (dy + 3) * 7 + (dx + 3)];
                if (dy >= -2 && dy <= 2 && dx >= -2 && dx <= 2)
                    f5 += v * wgt[9 + (dy + 2) * 5 + (dx + 2)];
                if (dy >= -1 && dy <= 1 && dx >= -1 && dx <= 1)
                    f3 += v * wgt[(dy + 1) * 3 + (dx + 1)];
            }
        size_t pix = (size_t)(h0 + ty + rr * 4) * 256 + (w0 + tx);
        size_t ob = (size_t)u * 768 * HW + pix;
        F[ob + (size_t) ch        * HW] = __float2half(f3);
        F[ob + (size_t)(256 + ch) * HW] = __float2half(f5);
        F[ob + (size_t)(512 + ch) * HW] = __float2half(f7);
    }
}

// ---------------- host launcher --------------------------------------------
extern "C" void kernel_launch(void* const* d_in, const int* in_sizes, int n_in,
                              void* d_out, int out_size) {
    const float* feats1 = (const float*)d_in[0];
    const float* feats2 = (const float*)d_in[1];
    const float* an_g  = (const float*)d_in[2];
    const float* an_b  = (const float*)d_in[3];
    const float* anc_g = (const float*)d_in[4];
    const float* anc_b = (const float*)d_in[5];
    const float* wq    = (const float*)d_in[6];
    const float* bq    = (const float*)d_in[7];
    const float* wkv   = (const float*)d_in[8];
    const float* bkv   = (const float*)d_in[9];
    const float* wo    = (const float*)d_in[10];
    const float* bo    = (const float*)d_in[11];
    const float* fn_g  = (const float*)d_in[12];
    const float* fn_b  = (const float*)d_in[13];
    const float* w_in  = (const float*)d_in[14];
    const float* b_in  = (const float*)d_in[15];
    const float* w_dw3 = (const float*)d_in[16];
    const float* b_dw3 = (const float*)d_in[17];
    const float* w_dw5 = (const float*)d_in[18];
    const float* b_dw5 = (const float*)d_in[19];
    const float* w_dw7 = (const float*)d_in[20];
    const float* b_dw7 = (const float*)d_in[21];
    const float* w_pw  = (const float*)d_in[22];
    const float* b_pw  = (const float*)d_in[23];
    const float* w_out = (const float*)d_in[24];
    const float* b_out = (const float*)d_in[25];
    float* dout = (float*)d_out;

    float *Q, *K, *V, *O, *Y, *WA, *SgA, *CA, *WIN, *SgI, *CI;
    __half *Fh, *WPWh;
    cudaGetSymbolAddress((void**)&Q,  g_Qb);
    cudaGetSymbolAddress((void**)&K,  g_Kb);
    cudaGetSymbolAddress((void**)&V,  g_Vb);
    cudaGetSymbolAddress((void**)&O,  g_Ob);
    cudaGetSymbolAddress((void**)&Y,  g_Y);
    cudaGetSymbolAddress((void**)&Fh, g_Fh);
    cudaGetSymbolAddress((void**)&WPWh, g_WPWh);
    cudaGetSymbolAddress((void**)&WA, g_WA);
    cudaGetSymbolAddress((void**)&SgA, g_SgA);
    cudaGetSymbolAddress((void**)&CA, g_CA);
    cudaGetSymbolAddress((void**)&WIN, g_WIN);
    cudaGetSymbolAddress((void**)&SgI, g_SgI);
    cudaGetSymbolAddress((void**)&CI, g_CI);

    const int smA = 3 * (128 * 20 + 16 * 136) * 4;   // BM=128/BN=128
    const int smB = 3 * (256 * 20 + 16 * 72)  * 4;   // BM=256/BN=64
    const int smH = 3 * (256 * 40 + 32 * 72)  * 2;   // fp16: 75264 B
    cudaFuncSetAttribute((const void*)gemm_tc<128, 0, 128, 128>, cudaFuncAttributeMaxDynamicSharedMemorySize, smA);
    cudaFuncSetAttribute((const void*)gemm_tc<128, 1, 128, 128>, cudaFuncAttributeMaxDynamicSharedMemorySize, smA);
    cudaFuncSetAttribute((const void*)gemm_tc<128, 2, 256, 64>,  cudaFuncAttributeMaxDynamicSharedMemorySize, smB);
    cudaFuncSetAttribute((const void*)gemm_pw_f16,               cudaFuncAttributeMaxDynamicSharedMemorySize, smH);
    cudaFuncSetAttribute((const void*)gemm_tc<256, 4, 128, 128>, cudaFuncAttributeMaxDynamicSharedMemorySize, smA);
    cudaFuncSetAttribute((const void*)attn_mma, cudaFuncAttributeMaxDynamicSharedMemorySize, ATTN_SMEM);

    // 1. weight prep (+ fp16 conversion of w_pw)
    prep_kernel<<<640, 128>>>(wq, bq, wkv, bkv, an_g, an_b, anc_g, anc_b,
                              w_in, b_in, fn_g, fn_b);
    convh_kernel<<<768, 256>>>(w_pw, WPWh, 256 * 768);
    // 2. fused LN(in-kernel stats) + q/kv projection
    gemm_tc<128, 0, 128, 128><<<dim3(128, 3, 4), 256, smA>>>(WA, nullptr, Q, K, V, SgA, CA,
                                                             feats1, feats2, nullptr, 1e-6f);
    // 3. attention
    attn_mma<<<1024, 256, ATTN_SMEM>>>(Q, K, V, O);
    // 4. output projection + residual(feats) -> d_out
    gemm_tc<128, 1, 128, 128><<<dim3(128, 1, 4), 256, smA>>>(wo, O, dout, nullptr, nullptr,
                                                             nullptr, nullptr,
                                                             feats1, feats2, bo, 0.f);
    // 5. fused LN(in-kernel stats) + w_in + SiLU -> Y
    gemm_tc<128, 2, 256, 64><<<dim3(256, 1, 4), 256, smB>>>(WIN, dout, Y, nullptr, nullptr,
                                                            SgI, CI, nullptr, nullptr, nullptr, 1e-5f);
    // 6. depthwise 3/5/7 -> Fh (768 channels, fp16)
    dw_kernel<<<dim3(4, 8, 1024), 256>>>(Y, w_dw3, b_dw3, w_dw5, b_dw5, w_dw7, b_dw7, Fh);
    // 7. pointwise GEMM (K=768, fp16 MMA) + SiLU + residual into Y
    gemm_pw_f16<<<dim3(256, 1, 4), 256, smH>>>(WPWh, Fh, Y, b_pw);
    // 8. w_out GEMM (K=256), accumulate into d_out
    gemm_tc<256, 4, 128, 128><<<dim3(128, 1, 4), 256, smA>>>(w_out, Y, dout, nullptr, nullptr,
                                                             nullptr, nullptr, nullptr, nullptr, b_out, 0.f);
}

// round 11
// speedup vs baseline: 1.2094x; 1.0324x over previous
#include <cuda_runtime.h>
#include <cuda_fp16.h>
#include <math.h>
#include <stdint.h>

#define HW 16384          // 64*256 pixels per (batch, channel) plane

// ---------------- scratch (static device globals; no allocation allowed) ----
__device__ __half g_Qh[4*128*HW];
__device__ __half g_Kh[4*128*HW];
__device__ __half g_Vh[4*128*HW];
__device__ float g_Ob[4*128*HW];
__device__ float g_Y [4*256*HW];
__device__ __half g_Fh[(size_t)4*768*HW];
__device__ __half g_WPWh[256*768];
__device__ float g_WA [384*128], g_SgA[384], g_CA[384];
__device__ float g_WIN[256*128], g_SgI[256], g_CI[256];

#define QSCALE (0.17677669529663687f * 1.4426950408889634f)

// ---------------- small helpers --------------------------------------------
__device__ __forceinline__ uint32_t smem_u32(const void* p) {
    return (uint32_t)__cvta_generic_to_shared(p);
}
__device__ __forceinline__ void cp16(uint32_t dst, const void* src) {
    asm volatile("cp.async.cg.shared.global [%0], [%1], 16;\n" :: "r"(dst), "l"(src));
}
__device__ __forceinline__ void cp_commit() { asm volatile("cp.async.commit_group;\n"); }
__device__ __forceinline__ void cp_wait1()  { asm volatile("cp.async.wait_group 1;\n"); }

__device__ __forceinline__ void mma_tf32(float* c, const uint32_t* a, const uint32_t* b) {
    asm volatile("mma.sync.aligned.m16n8k8.row.col.f32.tf32.tf32.f32 "
        "{%0,%1,%2,%3}, {%4,%5,%6,%7}, {%8,%9}, {%0,%1,%2,%3};"
        : "+f"(c[0]), "+f"(c[1]), "+f"(c[2]), "+f"(c[3])
        : "r"(a[0]), "r"(a[1]), "r"(a[2]), "r"(a[3]), "r"(b[0]), "r"(b[1]));
}
__device__ __forceinline__ void mma_f16(float* c, const uint32_t* a, const uint32_t* b) {
    asm volatile("mma.sync.aligned.m16n8k16.row.col.f32.f16.f16.f32 "
        "{%0,%1,%2,%3}, {%4,%5,%6,%7}, {%8,%9}, {%0,%1,%2,%3};"
        : "+f"(c[0]), "+f"(c[1]), "+f"(c[2]), "+f"(c[3])
        : "r"(a[0]), "r"(a[1]), "r"(a[2]), "r"(a[3]), "r"(b[0]), "r"(b[1]));
}
__device__ __forceinline__ void ldsm4(uint32_t* r, uint32_t addr) {
    asm volatile("ldmatrix.sync.aligned.m8n8.x4.shared.b16 {%0,%1,%2,%3}, [%4];"
        : "=r"(r[0]), "=r"(r[1]), "=r"(r[2]), "=r"(r[3]) : "r"(addr));
}
__device__ __forceinline__ void ldsm2t(uint32_t* r, uint32_t addr) {
    asm volatile("ldmatrix.sync.aligned.m8n8.x2.trans.shared.b16 {%0,%1}, [%2];"
        : "=r"(r[0]), "=r"(r[1]) : "r"(addr));
}
__device__ __forceinline__ float fexp2(float x) {
    float r; asm("ex2.approx.ftz.f32 %0, %1;" : "=f"(r) : "f"(x)); return r;
}
__device__ __forceinline__ uint32_t packh2(float a, float b) {
    __half2 h = __floats2half2_rn(a, b);
    return *(uint32_t*)&h;
}

// ---------------- fold LN gamma/beta into GEMM weights ---------------------
__global__ void prep_kernel(const float* __restrict__ wq,  const float* __restrict__ bq,
                            const float* __restrict__ wkv, const float* __restrict__ bkv,
                            const float* __restrict__ an_g, const float* __restrict__ an_b,
                            const float* __restrict__ anc_g, const float* __restrict__ anc_b,
                            const float* __restrict__ w_in, const float* __restrict__ b_in,
                            const float* __restrict__ fn_g, const float* __restrict__ fn_b) {
    int r = blockIdx.x, t = threadIdx.x;   // 640 blocks x 128 threads
    __shared__ float red[2][4];
    float wl, gg, bb, extra;
    float *Wdst, *Sgd, *Cd;
    if (r < 128)      { wl = wq [r*128 + t];        gg = an_g[t];  bb = an_b[t];  extra = bq [r];
                        Wdst = g_WA  + r*128;        Sgd = g_SgA + r;  Cd = g_CA + r; }
    else if (r < 384) { int rr = r - 128;
                        wl = wkv[rr*128 + t];       gg = anc_g[t]; bb = anc_b[t]; extra = bkv[rr];
                        Wdst = g_WA  + r*128;        Sgd = g_SgA + r;  Cd = g_CA + r; }
    else              { int rr = r - 384;
                        wl = w_in[rr*128 + t];      gg = fn_g[t];  bb = fn_b[t];  extra = b_in[rr];
                        Wdst = g_WIN + rr*128;       Sgd = g_SgI + rr; Cd = g_CI + rr; }
    float wg = wl * gg;
    Wdst[t] = wg;
    float s1 = wg, s2 = wl * bb;
    #pragma unroll
    for (int off = 16; off; off >>= 1) {
        s1 += __shfl_down_sync(0xffffffffu, s1, off);
        s2 += __shfl_down_sync(0xffffffffu, s2, off);
    }
    if ((t & 31) == 0) { red[0][t >> 5] = s1; red[1][t >> 5] = s2; }
    __syncthreads();
    if (t == 0) {
        float a = red[0][0] + red[0][1] + red[0][2] + red[0][3];
        float b = red[1][0] + red[1][1] + red[1][2] + red[1][3];
        *Sgd = a; *Cd = b + extra;
    }
}

// ---------------- convert w_pw to fp16 --------------------------------------
__global__ void convh_kernel(const float* __restrict__ W, __half* __restrict__ Wh, int n) {
    int i = blockIdx.x * 256 + threadIdx.x;
    if (i < n) Wh[i] = __float2half(W[i]);
}

// ---------------- tf32 tensor-core GEMM (proven config) ---------------------
// MODE 0 outputs fp16 Q (pre-scaled), K, V.
template<int K, int MODE, int BM, int BN>
__global__ void __launch_bounds__(256)
gemm_tc(const float* __restrict__ A, const float* __restrict__ B,
        float* __restrict__ O0, float* __restrict__ O1, float* __restrict__ O2,
        const float* __restrict__ Sg, const float* __restrict__ Cst,
        const float* __restrict__ X1, const float* __restrict__ X2,
        const float* __restrict__ bias, float eps) {
    constexpr int BK = 16, ST = 3;
    constexpr int KT = K / BK;
    constexpr int ASP = 20;
    constexpr int BSP = BN + 8;
    constexpr int ASZ = BM * ASP;
    constexpr int BSZ = BK * BSP;
    constexpr int NA = BM / 64;
    constexpr int NB = BN / 64;
    constexpr int WN = (BM == 128) ? 4 : 2;
    constexpr bool STATS = (MODE == 0 || MODE == 2);
    constexpr int SH = (BN == 64) ? 4 : 2;
    constexpr int RT = 16 / SH;
    extern __shared__ float smf[];
    float* As = smf;
    float* Bs = smf + ST * ASZ;
    __shared__ float sst[STATS ? 2 : 1][STATS ? SH : 1][STATS ? BN : 1];

    int tid = threadIdx.x, lane = tid & 31, wid = tid >> 5;
    int wm = wid / WN, wn = wid % WN;
    int n0 = blockIdx.x * BN, m0 = blockIdx.y * BM, u = blockIdx.z;
    const float* Ap = A + (size_t)m0 * K;
    const float* Bp;
    if (MODE == 0) Bp = (u < 2 ? X1 : X2) + (size_t)(u & 1) * 128 * HW + n0;
    else           Bp = B + (size_t)u * K * HW + n0;

    float acc[4][4][4];
    #pragma unroll
    for (int i = 0; i < 4; i++)
        #pragma unroll
        for (int j = 0; j < 4; j++)
            #pragma unroll
            for (int e = 0; e < 4; e++) acc[i][j][e] = 0.f;

    int ar[NA], ac[NA], br[NB], bc[NB];
    #pragma unroll
    for (int i = 0; i < NA; i++) {
        int idx = tid + i * 256;
        ar[i] = idx >> 2; ac[i] = (idx & 3) << 2;
    }
    #pragma unroll
    for (int i = 0; i < NB; i++) {
        int idx = tid + i * 256;
        br[i] = idx / (BN / 4); bc[i] = (idx % (BN / 4)) << 2;
    }
    int sc = tid % BN, sg = tid / BN;
    float s_sum = 0.f, s_sq = 0.f;
    int lm = lane >> 3;
    int loff = (((lane & 7) + (lm & 1) * 8)) * ASP + (lm >> 1) * 4;
    uint32_t as_base = smem_u32(As);

    #define PREFETCH(sidx, k0)                                                     \
        {   _Pragma("unroll")                                                      \
            for (int i = 0; i < NA; i++)                                           \
                cp16(smem_u32(&As[(sidx) * ASZ + ar[i] * ASP + ac[i]]),            \
                     Ap + (size_t)ar[i] * K + (k0) + ac[i]);                       \
            _Pragma("unroll")                                                      \
            for (int i = 0; i < NB; i++)                                           \
                cp16(smem_u32(&Bs[(sidx) * BSZ + br[i] * BSP + bc[i]]),            \
                     Bp + (size_t)((k0) + br[i]) * HW + bc[i]);                    \
        }

    PREFETCH(0, 0); cp_commit();
    if (KT > 1) PREFETCH(1, BK);
    cp_commit();

    for (int kt = 0; kt < KT; kt++) {
        cp_wait1();
        __syncthreads();
        int st = kt % ST;
        const float* bs = Bs + st * BSZ;
        if (STATS) {
            #pragma unroll
            for (int rr = 0; rr < RT; rr++) {
                float v = bs[(sg * RT + rr) * BSP + sc];
                s_sum += v; s_sq += v * v;
            }
        }
        uint32_t abase = as_base + (uint32_t)(st * ASZ + wm * 64 * ASP + loff) * 4;
        #pragma unroll
        for (int s8 = 0; s8 < 2; s8++) {
            uint32_t a[4][4], b[4][2];
            #pragma unroll
            for (int mt = 0; mt < 4; mt++)
                ldsm4(a[mt], abase + (uint32_t)(mt * 16 * ASP + s8 * 8) * 4);
            #pragma unroll
            for (int nt = 0; nt < 4; nt++) {
                const float* bp = bs + (s8 * 8 + (lane & 3)) * BSP
                                     + wn * 32 + nt * 8 + (lane >> 2);
                b[nt][0] = __float_as_uint(bp[0]);
                b[nt][1] = __float_as_uint(bp[4 * BSP]);
            }
            #pragma unroll
            for (int mt = 0; mt < 4; mt++)
                #pragma unroll
                for (int nt = 0; nt < 4; nt++)
                    mma_tf32(acc[mt][nt], a[mt], b[nt]);
        }
        if (kt + 2 < KT) PREFETCH((kt + 2) % ST, (kt + 2) * BK);
        cp_commit();
    }
    #undef PREFETCH

    if (STATS) {
        sst[0][sg][sc] = s_sum;
        sst[1][sg][sc] = s_sq;
        __syncthreads();
        if (tid < BN) {
            float S = 0.f, SS = 0.f;
            #pragma unroll
            for (int g = 0; g < SH; g++) { S += sst[0][g][tid]; SS += sst[1][g][tid]; }
            float m = S * (1.f / 128.f);
            float var = SS * (1.f / 128.f) - m * m;
            sst[0][0][tid] = m;
            sst[1][0][tid] = rsqrtf(var + eps);
        }
        __syncthreads();
    }

    #pragma unroll
    for (int mt = 0; mt < 4; mt++) {
        #pragma unroll
        for (int half = 0; half < 2; half++) {
            int row = m0 + wm * 64 + mt * 16 + (lane >> 2) + half * 8;
            float sgr = 0.f, cstr = 0.f, br2 = 0.f;
            if (MODE == 0 || MODE == 2) { sgr = Sg[row]; cstr = Cst[row]; }
            else br2 = bias[row];
            #pragma unroll
            for (int nt = 0; nt < 4; nt++) {
                #pragma unroll
                for (int e = 0; e < 2; e++) {
                    int pl = wn * 32 + nt * 8 + (lane & 3) * 2 + e;
                    int p = n0 + pl;
                    float v = acc[mt][nt][half * 2 + e];
                    if (MODE == 0) {
                        float mv = sst[0][0][pl], rv = sst[1][0][pl];
                        v = rv * v + (cstr - mv * rv * sgr);
                        if (row < 128)
                            ((__half*)O0)[((size_t)u * 128 + row) * HW + p] = __float2half(v * QSCALE);
                        else if (row < 256)
                            ((__half*)O1)[((size_t)(u ^ 2) * 128 + (row - 128)) * HW + p] = __float2half(v);
                        else
                            ((__half*)O2)[((size_t)(u ^ 2) * 128 + (row - 256)) * HW + p] = __float2half(v);
                    } else if (MODE == 1) {
                        float res = ((u < 2 ? X1 : X2))[((size_t)(u & 1) * 128 + row) * HW + p];
                        size_t idx = ((size_t)u * 128 + row) * HW + p;
                        O0[idx] = v + br2 + res;
                    } else if (MODE == 2) {
                        float mv = sst[0][0][pl], rv = sst[1][0][pl];
                        v = rv * v + (cstr - mv * rv * sgr);
                        v = v / (1.f + __expf(-v));
                        O0[((size_t)u * 256 + row) * HW + p] = v;
                    } else {
                        v += br2;
                        size_t idx = ((size_t)u * 128 + row) * HW + p;
                        O0[idx] += v;
                    }
                }
            }
        }
    }
}

// ---------------- fp16 GEMM for the pointwise conv --------------------------
__global__ void __launch_bounds__(256)
gemm_pw_f16(const __half* __restrict__ A, const __half* __restrict__ B,
            float* __restrict__ Y, const float* __restrict__ bias) {
    constexpr int K = 768, BN = 64, BK = 32, ST = 3;
    constexpr int KT = K / BK;           // 24
    constexpr int ASPH = 40;
    constexpr int BSPH = BN + 8;         // 72
    constexpr int ASZ = 256 * ASPH;
    constexpr int BSZ = BK * BSPH;
    extern __shared__ __half smh[];
    __half* As = smh;
    __half* Bs = smh + ST * ASZ;

    int tid = threadIdx.x, lane = tid & 31, wid = tid >> 5;
    int wm = wid >> 1, wn = wid & 1;
    int n0 = blockIdx.x * BN, u = blockIdx.z;
    const __half* Bp = B + (size_t)u * K * HW + n0;

    float acc[4][4][4];
    #pragma unroll
    for (int i = 0; i < 4; i++)
        #pragma unroll
        for (int j = 0; j < 4; j++)
            #pragma unroll
            for (int e = 0; e < 4; e++) acc[i][j][e] = 0.f;

    int aro[4], aco[4];
    #pragma unroll
    for (int i = 0; i < 4; i++) {
        int idx = tid + i * 256;
        aro[i] = idx >> 2; aco[i] = (idx & 3) << 3;
    }
    int brw = tid >> 3, bcl = (tid & 7) << 3;

    int arow_l = lane & 15, acol_l = (lane >> 4) << 3;
    int brow_l = (lane & 7) + ((lane >> 3) & 1) * 8;
    uint32_t as_base = smem_u32(As);
    uint32_t bs_base = smem_u32(Bs);

    #define PF16(sidx, k0)                                                         \
        {   _Pragma("unroll")                                                      \
            for (int i = 0; i < 4; i++)                                            \
                cp16(smem_u32(&As[(sidx) * ASZ + aro[i] * ASPH + aco[i]]),         \
                     A + (size_t)aro[i] * K + (k0) + aco[i]);                      \
            cp16(smem_u32(&Bs[(sidx) * BSZ + brw * BSPH + bcl]),                   \
                 Bp + (size_t)((k0) + brw) * HW + bcl);                            \
        }

    PF16(0, 0); cp_commit();
    PF16(1, BK); cp_commit();

    for (int kt = 0; kt < KT; kt++) {
        cp_wait1();
        __syncthreads();
        int st = kt % ST;
        uint32_t abase = as_base + (uint32_t)(st * ASZ + (wm * 64 + arow_l) * ASPH + acol_l) * 2;
        uint32_t bbase = bs_base + (uint32_t)(st * BSZ + brow_l * BSPH + wn * 32) * 2;
        #pragma unroll
        for (int s16 = 0; s16 < 2; s16++) {
            uint32_t a[4][4], b[4][2];
            #pragma unroll
            for (int mt = 0; mt < 4; mt++)
                ldsm4(a[mt], abase + (uint32_t)(mt * 16 * ASPH + s16 * 16) * 2);
            #pragma unroll
            for (int nt = 0; nt < 4; nt++)
                ldsm2t(b[nt], bbase + (uint32_t)(s16 * 16 * BSPH + nt * 8) * 2);
            #pragma unroll
            for (int mt = 0; mt < 4; mt++)
                #pragma unroll
                for (int nt = 0; nt < 4; nt++)
                    mma_f16(acc[mt][nt], a[mt], b[nt]);
        }
        if (kt + 2 < KT) PF16((kt + 2) % ST, (kt + 2) * BK);
        cp_commit();
    }
    #undef PF16

    #pragma unroll
    for (int mt = 0; mt < 4; mt++) {
        #pragma unroll
        for (int half = 0; half < 2; half++) {
            int row = wm * 64 + mt * 16 + (lane >> 2) + half * 8;
            float br2 = bias[row];
            #pragma unroll
            for (int nt = 0; nt < 4; nt++) {
                #pragma unroll
                for (int e = 0; e < 2; e++) {
                    int p = n0 + wn * 32 + nt * 8 + (lane & 3) * 2 + e;
                    float v = acc[mt][nt][half * 2 + e] + br2;
                    v = v / (1.f + __expf(-v));
                    size_t idx = ((size_t)u * 256 + row) * HW + p;
                    Y[idx] = Y[idx] + v;
                }
            }
        }
    }
}

// ---------------- fp16 flash attention (register-direct P reuse) -------------
// smem (halves): Qs[256*40], Vs[256*40], Kt[32*264]; then V2[256]f, Vsum[32]f
#define AT2_QS 0
#define AT2_VS 10240
#define AT2_KT 20480
#define AT2_HALVES 28928
#define ATTN2_SMEM (AT2_HALVES * 2 + 256 * 4 + 32 * 4)

__global__ void __launch_bounds__(256, 2)
attn_f16(const __half* __restrict__ Q, const __half* __restrict__ K,
         const __half* __restrict__ V, float* __restrict__ O) {
    int blk = blockIdx.x;                  // b*256 + n*64 + h
    int h = blk & 63, n = (blk >> 6) & 3, b = blk >> 8;
    size_t base = ((size_t)(b * 128 + n * 32) * 64 + h) * 256;
    extern __shared__ __half smh2[];
    __half* Qs = smh2 + AT2_QS;            // [i][d] pitch 40
    __half* Vs = smh2 + AT2_VS;            // [j][d] pitch 40
    __half* Kt = smh2 + AT2_KT;            // [d][j] pitch 264
    float* V2 = (float*)(smh2 + AT2_HALVES);
    float* Vsum = V2 + 256;
    int tid = threadIdx.x, lane = tid & 31, w = tid >> 5;

    #pragma unroll 4
    for (int dd = 0; dd < 32; dd++) {
        Qs[tid * 40 + dd] = Q[base + (size_t)dd * HW + tid];
        Vs[tid * 40 + dd] = V[base + (size_t)dd * HW + tid];
    }
    #pragma unroll
    for (int i = 0; i < 4; i++) {
        int idx = tid + i * 256;
        int row = idx >> 5, seg = idx & 31;
        *(uint4*)&Kt[row * 264 + seg * 8] =
            *(const uint4*)&K[base + (size_t)row * HW + seg * 8];
    }
    __syncthreads();
    {
        float s = 0.f;
        #pragma unroll 8
        for (int jj = 0; jj < 32; jj++) s += __half2float(Vs[(w * 32 + jj) * 40 + lane]);
        V2[w * 32 + lane] = s;
    }

    int i0 = w * 32;
    uint32_t qa[2][2][4];
    #pragma unroll
    for (int mt = 0; mt < 2; mt++)
        #pragma unroll
        for (int dk = 0; dk < 2; dk++)
            ldsm4(qa[mt][dk],
                  smem_u32(&Qs[(i0 + mt * 16 + (lane & 15)) * 40 + dk * 16 + ((lane >> 4) << 3)]));
    int brow = (lane & 7) + ((lane >> 3) & 1) * 8;

    float l0[2] = {0.f, 0.f}, l1[2] = {0.f, 0.f};
    float o[2][4][4];
    #pragma unroll
    for (int mt = 0; mt < 2; mt++)
        #pragma unroll
        for (int dt = 0; dt < 4; dt++)
            #pragma unroll
            for (int e = 0; e < 4; e++) o[mt][dt][e] = 0.f;

    for (int j0 = 0; j0 < 256; j0 += 16) {
        float s[2][2][4];
        #pragma unroll
        for (int mt = 0; mt < 2; mt++)
            #pragma unroll
            for (int jh = 0; jh < 2; jh++)
                #pragma unroll
                for (int e = 0; e < 4; e++) s[mt][jh][e] = 0.f;
        uint32_t bS[2][2][2];
        #pragma unroll
        for (int dk = 0; dk < 2; dk++)
            #pragma unroll
            for (int jh = 0; jh < 2; jh++)
                ldsm2t(bS[dk][jh], smem_u32(&Kt[(dk * 16 + brow) * 264 + j0 + jh * 8]));
        #pragma unroll
        for (int mt = 0; mt < 2; mt++)
            #pragma unroll
            for (int jh = 0; jh < 2; jh++)
                #pragma unroll
                for (int dk = 0; dk < 2; dk++)
                    mma_f16(s[mt][jh], qa[mt][dk], bS[dk][jh]);
        // softmax numerator -> fp16 A fragment (register-direct)
        uint32_t pa[2][4];
        #pragma unroll
        for (int mt = 0; mt < 2; mt++) {
            float p00 = fexp2(s[mt][0][0]), p01 = fexp2(s[mt][0][1]);
            float p02 = fexp2(s[mt][0][2]), p03 = fexp2(s[mt][0][3]);
            float p10 = fexp2(s[mt][1][0]), p11 = fexp2(s[mt][1][1]);
            float p12 = fexp2(s[mt][1][2]), p13 = fexp2(s[mt][1][3]);
            l0[mt] += p00 + p01 + p10 + p11;
            l1[mt] += p02 + p03 + p12 + p13;
            pa[mt][0] = packh2(p00, p01);
            pa[mt][1] = packh2(p02, p03);
            pa[mt][2] = packh2(p10, p11);
            pa[mt][3] = packh2(p12, p13);
        }
        uint32_t bV[4][2];
        #pragma unroll
        for (int dt = 0; dt < 4; dt++)
            ldsm2t(bV[dt], smem_u32(&Vs[(j0 + brow) * 40 + dt * 8]));
        #pragma unroll
        for (int mt = 0; mt < 2; mt++)
            #pragma unroll
            for (int dt = 0; dt < 4; dt++)
                mma_f16(o[mt][dt], pa[mt], bV[dt]);
    }
    // finalize row sums across the quad (lanes sharing the same row)
    #pragma unroll
    for (int mt = 0; mt < 2; mt++) {
        l0[mt] += __shfl_xor_sync(0xffffffffu, l0[mt], 1);
        l0[mt] += __shfl_xor_sync(0xffffffffu, l0[mt], 2);
        l1[mt] += __shfl_xor_sync(0xffffffffu, l1[mt], 1);
        l1[mt] += __shfl_xor_sync(0xffffffffu, l1[mt], 2);
    }

    __syncthreads();
    float* Ow = (float*)smh2 + w * 32 * 36;     // reuse Qs/Vs region
    #pragma unroll
    for (int mt = 0; mt < 2; mt++)
        #pragma unroll
        for (int hf = 0; hf < 2; hf++) {
            float inv = 1.f / (hf == 0 ? l0[mt] : l1[mt]);
            int row = mt * 16 + (lane >> 2) + hf * 8;
            #pragma unroll
            for (int dt = 0; dt < 4; dt++) {
                Ow[row * 36 + dt * 8 + (lane & 3) * 2]     = o[mt][dt][hf * 2]     * inv;
                Ow[row * 36 + dt * 8 + (lane & 3) * 2 + 1] = o[mt][dt][hf * 2 + 1] * inv;
            }
        }
    if (tid < 32) {
        float s = 0.f;
        #pragma unroll
        for (int ww = 0; ww < 8; ww++) s += V2[ww * 32 + tid];
        Vsum[tid] = s;
    }
    __syncthreads();
    const float eps = 1e-6f;
    const float norm = 1.f / (1.f + 256.f * eps);
    #pragma unroll 4
    for (int d = 0; d < 32; d++) {
        float val = (Ow[lane * 36 + d] + eps * Vsum[d]) * norm;
        O[base + (size_t)d * HW + i0 + lane] = val;
    }
}

// ---------------- depthwise 3x3 / 5x5 / 7x7 -> half F -----------------------
__global__ void dw_kernel(const float* __restrict__ Y,
                          const float* __restrict__ w3, const float* __restrict__ b3,
                          const float* __restrict__ w5, const float* __restrict__ b5,
                          const float* __restrict__ w7, const float* __restrict__ b7,
                          __half* __restrict__ F) {
    __shared__ float S[14][70];
    __shared__ float wgt[84];
    int z = blockIdx.z; int ch = z & 255; int u = z >> 8;
    int w0 = blockIdx.x * 64, h0 = blockIdx.y * 8;
    int tid = threadIdx.x;
    if (tid < 9)       wgt[tid] = w3[ch * 9 + tid];
    else if (tid < 34) wgt[tid] = w5[ch * 25 + tid - 9];
    else if (tid < 83) wgt[tid] = w7[ch * 49 + tid - 34];
    const float* Yp = Y + ((size_t)u * 256 + ch) * HW;
    for (int i = tid; i < 980; i += 256) {
        int r = i / 70, c = i % 70;
        int gh = h0 - 3 + r, gw = w0 - 3 + c;
        float v = 0.f;
        if ((unsigned)gh < 64u && (unsigned)gw < 256u) v = Yp[gh * 256 + gw];
        S[r][c] = v;
    }
    __syncthreads();
    int tx = tid & 63, ty = tid >> 6;
    float bb3 = b3[ch], bb5 = b5[ch], bb7 = b7[ch];
    #pragma unroll
    for (int rr = 0; rr < 2; rr++) {
        int rc = ty + rr * 4 + 3, cc = tx + 3;
        float f3 = bb3, f5 = bb5, f7 = bb7;
        #pragma unroll
        for (int dy = -3; dy <= 3; dy++)
            #pragma unroll
            for (int dx = -3; dx <= 3; dx++) {
                float v = S[rc + dy][cc + dx];
                f7 += v * wgt[34 + (dy + 3) * 7 + (dx + 3)];
                if (dy >= -2 && dy <= 2 && dx >= -2 && dx <= 2)
                    f5 += v * wgt[9 + (dy + 2) * 5 + (dx + 2)];
                if (dy >= -1 && dy <= 1 && dx >= -1 && dx <= 1)
                    f3 += v * wgt[(dy + 1) * 3 + (dx + 1)];
            }
        size_t pix = (size_t)(h0 + ty + rr * 4) * 256 + (w0 + tx);
        size_t ob = (size_t)u * 768 * HW + pix;
        F[ob + (size_t) ch        * HW] = __float2half(f3);
        F[ob + (size_t)(256 + ch) * HW] = __float2half(f5);
        F[ob + (size_t)(512 + ch) * HW] = __float2half(f7);
    }
}

// ---------------- host launcher --------------------------------------------
extern "C" void kernel_launch(void* const* d_in, const int* in_sizes, int n_in,
                              void* d_out, int out_size) {
    const float* feats1 = (const float*)d_in[0];
    const float* feats2 = (const float*)d_in[1];
    const float* an_g  = (const float*)d_in[2];
    const float* an_b  = (const float*)d_in[3];
    const float* anc_g = (const float*)d_in[4];
    const float* anc_b = (const float*)d_in[5];
    const float* wq    = (const float*)d_in[6];
    const float* bq    = (const float*)d_in[7];
    const float* wkv   = (const float*)d_in[8];
    const float* bkv   = (const float*)d_in[9];
    const float* wo    = (const float*)d_in[10];
    const float* bo    = (const float*)d_in[11];
    const float* fn_g  = (const float*)d_in[12];
    const float* fn_b  = (const float*)d_in[13];
    const float* w_in  = (const float*)d_in[14];
    const float* b_in  = (const float*)d_in[15];
    const float* w_dw3 = (const float*)d_in[16];
    const float* b_dw3 = (const float*)d_in[17];
    const float* w_dw5 = (const float*)d_in[18];
    const float* b_dw5 = (const float*)d_in[19];
    const float* w_dw7 = (const float*)d_in[20];
    const float* b_dw7 = (const float*)d_in[21];
    const float* w_pw  = (const float*)d_in[22];
    const float* b_pw  = (const float*)d_in[23];
    const float* w_out = (const float*)d_in[24];
    const float* b_out = (const float*)d_in[25];
    float* dout = (float*)d_out;

    float *O, *Y, *WA, *SgA, *CA, *WIN, *SgI, *CI;
    __half *Qh, *Kh, *Vh, *Fh, *WPWh;
    cudaGetSymbolAddress((void**)&Qh, g_Qh);
    cudaGetSymbolAddress((void**)&Kh, g_Kh);
    cudaGetSymbolAddress((void**)&Vh, g_Vh);
    cudaGetSymbolAddress((void**)&O,  g_Ob);
    cudaGetSymbolAddress((void**)&Y,  g_Y);
    cudaGetSymbolAddress((void**)&Fh, g_Fh);
    cudaGetSymbolAddress((void**)&WPWh, g_WPWh);
    cudaGetSymbolAddress((void**)&WA, g_WA);
    cudaGetSymbolAddress((void**)&SgA, g_SgA);
    cudaGetSymbolAddress((void**)&CA, g_CA);
    cudaGetSymbolAddress((void**)&WIN, g_WIN);
    cudaGetSymbolAddress((void**)&SgI, g_SgI);
    cudaGetSymbolAddress((void**)&CI, g_CI);

    const int smA = 3 * (128 * 20 + 16 * 136) * 4;   // BM=128/BN=128
    const int smB = 3 * (256 * 20 + 16 * 72)  * 4;   // BM=256/BN=64
    const int smH = 3 * (256 * 40 + 32 * 72)  * 2;   // fp16 pw: 75264 B
    cudaFuncSetAttribute((const void*)gemm_tc<128, 0, 128, 128>, cudaFuncAttributeMaxDynamicSharedMemorySize, smA);
    cudaFuncSetAttribute((const void*)gemm_tc<128, 1, 128, 128>, cudaFuncAttributeMaxDynamicSharedMemorySize, smA);
    cudaFuncSetAttribute((const void*)gemm_tc<128, 2, 256, 64>,  cudaFuncAttributeMaxDynamicSharedMemorySize, smB);
    cudaFuncSetAttribute((const void*)gemm_pw_f16,               cudaFuncAttributeMaxDynamicSharedMemorySize, smH);
    cudaFuncSetAttribute((const void*)gemm_tc<256, 4, 128, 128>, cudaFuncAttributeMaxDynamicSharedMemorySize, smA);
    cudaFuncSetAttribute((const void*)attn_f16, cudaFuncAttributeMaxDynamicSharedMemorySize, ATTN2_SMEM);

    // 1. weight prep (+ fp16 conversion of w_pw)
    prep_kernel<<<640, 128>>>(wq, bq, wkv, bkv, an_g, an_b, anc_g, anc_b,
                              w_in, b_in, fn_g, fn_b);
    convh_kernel<<<768, 256>>>(w_pw, WPWh, 256 * 768);
    // 2. fused LN + q/kv projection -> fp16 Q (pre-scaled), K, V
    gemm_tc<128, 0, 128, 128><<<dim3(128, 3, 4), 256, smA>>>(WA, nullptr,
                                                             (float*)Qh, (float*)Kh, (float*)Vh,
                                                             SgA, CA, feats1, feats2, nullptr, 1e-6f);
    // 3. fp16 flash attention
    attn_f16<<<1024, 256, ATTN2_SMEM>>>(Qh, Kh, Vh, O);
    // 4. output projection + residual(feats) -> d_out
    gemm_tc<128, 1, 128, 128><<<dim3(128, 1, 4), 256, smA>>>(wo, O, dout, nullptr, nullptr,
                                                             nullptr, nullptr,
                                                             feats1, feats2, bo, 0.f);
    // 5. fused LN + w_in + SiLU -> Y
    gemm_tc<128, 2, 256, 64><<<dim3(256, 1, 4), 256, smB>>>(WIN, dout, Y, nullptr, nullptr,
                                                            SgI, CI, nullptr, nullptr, nullptr, 1e-5f);
    // 6. depthwise 3/5/7 -> Fh (768 channels, fp16)
    dw_kernel<<<dim3(4, 8, 1024), 256>>>(Y, w_dw3, b_dw3, w_dw5, b_dw5, w_dw7, b_dw7, Fh);
    // 7. pointwise GEMM (K=768, fp16 MMA) + SiLU + residual into Y
    gemm_pw_f16<<<dim3(256, 1, 4), 256, smH>>>(WPWh, Fh, Y, b_pw);
    // 8. w_out GEMM (K=256), accumulate into d_out
    gemm_tc<256, 4, 128, 128><<<dim3(128, 1, 4), 256, smA>>>(w_out, Y, dout, nullptr, nullptr,
                                                             nullptr, nullptr, nullptr, nullptr, b_out, 0.f);
}